// round 1
// baseline (speedup 1.0000x reference)
#include <cuda_runtime.h>
#include <math.h>
#include <stdint.h>

// Problem constants
#define BATCH 2
#define NSEQ  2048
#define DMODEL 2048
#define NH    32
#define NKVH  8
#define HD    64
#define GRP   4          // NH / NKVH
#define ROWS  4096       // BATCH * NSEQ

// ---------------------------------------------------------------------------
// Scratch (device globals -- no allocation allowed anywhere)
// ---------------------------------------------------------------------------
__device__ float g_Q[(size_t)ROWS * DMODEL];          // 32 MB  (B*N, H*HD)
__device__ float g_K[(size_t)ROWS * (NKVH * HD)];     //  8 MB  (B*N, KVH*HD)
__device__ float g_V[(size_t)ROWS * (NKVH * HD)];     //  8 MB
__device__ float g_O[(size_t)ROWS * DMODEL];          // 32 MB  attention output

// ---------------------------------------------------------------------------
// SGEMM: C[M,N] = A[M,K] @ B[K,N], all row-major fp32.
// 128x128 block tile, BK=8, 256 threads, 8x8 register tile.
// Requires M%128==0, N%128==0, K%8==0 (true for all our shapes).
// ---------------------------------------------------------------------------
__global__ __launch_bounds__(256) void sgemm128(
    const float* __restrict__ A, const float* __restrict__ B,
    float* __restrict__ C, int M, int N, int K)
{
    __shared__ float As[8][128];   // transposed A tile: As[k][m]
    __shared__ float Bs[8][128];   // Bs[k][n]

    const int tid  = threadIdx.x;
    const int bx   = blockIdx.x;   // N-tile
    const int by   = blockIdx.y;   // M-tile
    const int tcol = tid & 15;     // 0..15 -> 8 cols each
    const int trow = tid >> 4;     // 0..15 -> 8 rows each

    // A tile load: 128 rows x 8 cols = 256 float4 (along K)
    const int aRow = tid >> 1;           // 0..127
    const int aCol = (tid & 1) << 2;     // 0 or 4
    // B tile load: 8 rows x 128 cols = 256 float4 (along N)
    const int bRow = tid >> 5;           // 0..7
    const int bCol = (tid & 31) << 2;    // 0..124

    const float* Ab = A + (size_t)(by * 128) * K;
    const float* Bb = B + (size_t)(bx * 128);

    float acc[8][8];
#pragma unroll
    for (int i = 0; i < 8; i++)
#pragma unroll
        for (int j = 0; j < 8; j++) acc[i][j] = 0.f;

    for (int k0 = 0; k0 < K; k0 += 8) {
        float4 a4 = *(const float4*)(Ab + (size_t)aRow * K + k0 + aCol);
        As[aCol + 0][aRow] = a4.x;
        As[aCol + 1][aRow] = a4.y;
        As[aCol + 2][aRow] = a4.z;
        As[aCol + 3][aRow] = a4.w;
        *(float4*)&Bs[bRow][bCol] =
            *(const float4*)(Bb + (size_t)(k0 + bRow) * N + bCol);
        __syncthreads();

#pragma unroll
        for (int kk = 0; kk < 8; kk++) {
            float4 a0 = *(float4*)&As[kk][trow * 8];
            float4 a1 = *(float4*)&As[kk][trow * 8 + 4];
            float4 b0 = *(float4*)&Bs[kk][tcol * 8];
            float4 b1 = *(float4*)&Bs[kk][tcol * 8 + 4];
            float ra[8] = {a0.x, a0.y, a0.z, a0.w, a1.x, a1.y, a1.z, a1.w};
            float rb[8] = {b0.x, b0.y, b0.z, b0.w, b1.x, b1.y, b1.z, b1.w};
#pragma unroll
            for (int i = 0; i < 8; i++)
#pragma unroll
                for (int j = 0; j < 8; j++)
                    acc[i][j] += ra[i] * rb[j];
        }
        __syncthreads();
    }

    float* Cb = C + (size_t)(by * 128 + trow * 8) * N + bx * 128 + tcol * 8;
#pragma unroll
    for (int i = 0; i < 8; i++) {
        *(float4*)(Cb + (size_t)i * N) =
            make_float4(acc[i][0], acc[i][1], acc[i][2], acc[i][3]);
        *(float4*)(Cb + (size_t)i * N + 4) =
            make_float4(acc[i][4], acc[i][5], acc[i][6], acc[i][7]);
    }
}

// ---------------------------------------------------------------------------
// RoPE (interleaved even/odd pairs), in place.
// X: (ROWS, cols) where cols = heads*HD; fc/fs: (NSEQ, HD/2).
// One thread per (row, pair).
// ---------------------------------------------------------------------------
__global__ void rope_k(float* __restrict__ X,
                       const float* __restrict__ fc,
                       const float* __restrict__ fs,
                       int cols, int total)
{
    int idx = blockIdx.x * blockDim.x + threadIdx.x;
    if (idx >= total) return;
    const int half = cols >> 1;
    int row = idx / half;
    int c   = idx - row * half;        // head*32 + p
    int p   = c & 31;                  // HD/2 - 1
    int n   = row & (NSEQ - 1);
    float cv = fc[n * 32 + p];
    float sv = fs[n * 32 + p];
    float2* ptr = (float2*)(X + (size_t)row * cols) + c;
    float2 x2 = *ptr;
    float2 r2;
    r2.x = x2.x * cv - x2.y * sv;
    r2.y = x2.x * sv + x2.y * cv;
    *ptr = r2;
}

// ---------------------------------------------------------------------------
// Flash attention, fp32, causal, GQA (4 q-heads per kv-head).
// grid = (NSEQ/64, NH, BATCH); 256 threads.
// Thread (row = tid>>2, tx = tid&3): owns query row qt*64+row, dims [16*tx,16*tx+16).
// Scores for the 64-key tile are partial-summed per tx then reduced with
// __shfl_xor so every thread holds the full 64 probabilities in registers.
// ---------------------------------------------------------------------------
__global__ __launch_bounds__(256) void attn64(
    const float* __restrict__ Q, const float* __restrict__ Kg,
    const float* __restrict__ Vg, float* __restrict__ O)
{
    __shared__ float sK[64 * 64];
    __shared__ float sV[64 * 64];

    const int qt = blockIdx.x, h = blockIdx.y, b = blockIdx.z;
    const int kvh = h >> 2;
    const int tid = threadIdx.x;
    const int row = tid >> 2;
    const int tx  = tid & 3;
    const int qi  = qt * 64 + row;

    // q registers: this thread's 16 dims of its query row
    float qv[16];
    {
        const float* qptr =
            Q + (size_t)(b * NSEQ + qi) * DMODEL + h * HD + tx * 16;
#pragma unroll
        for (int i = 0; i < 4; i++) {
            float4 t4 = *(const float4*)(qptr + i * 4);
            qv[i * 4 + 0] = t4.x; qv[i * 4 + 1] = t4.y;
            qv[i * 4 + 2] = t4.z; qv[i * 4 + 3] = t4.w;
        }
    }

    float o[16];
#pragma unroll
    for (int i = 0; i < 16; i++) o[i] = 0.f;
    float m = -1e30f, l = 0.f;

    const int nT = qt + 1;
    for (int t = 0; t < nT; t++) {
        __syncthreads();   // protect sK/sV from previous iteration's readers
        {
            const float* kb =
                Kg + (size_t)(b * NSEQ + t * 64) * (NKVH * HD) + kvh * HD;
            const float* vb =
                Vg + (size_t)(b * NSEQ + t * 64) * (NKVH * HD) + kvh * HD;
#pragma unroll
            for (int i = 0; i < 4; i++) {
                int idx = tid + i * 256;       // 0..1023 float4 slots
                int r = idx >> 4;
                int c = (idx & 15) << 2;
                *(float4*)&sK[r * 64 + c] =
                    *(const float4*)(kb + (size_t)r * (NKVH * HD) + c);
                *(float4*)&sV[r * 64 + c] =
                    *(const float4*)(vb + (size_t)r * (NKVH * HD) + c);
            }
        }
        __syncthreads();

        // partial scores over this thread's 16 dims, for all 64 keys
        float s[64];
#pragma unroll
        for (int j = 0; j < 64; j++) {
            const float4* kp = (const float4*)&sK[j * 64 + tx * 16];
            float acc = 0.f;
#pragma unroll
            for (int i = 0; i < 4; i++) {
                float4 kk = kp[i];
                acc += qv[i * 4 + 0] * kk.x + qv[i * 4 + 1] * kk.y +
                       qv[i * 4 + 2] * kk.z + qv[i * 4 + 3] * kk.w;
            }
            s[j] = acc;
        }
        // reduce across the 4 tx threads (lanes differ in bits 0..1)
#pragma unroll
        for (int j = 0; j < 64; j++) {
            s[j] += __shfl_xor_sync(0xffffffffu, s[j], 1);
            s[j] += __shfl_xor_sync(0xffffffffu, s[j], 2);
        }

        // causal mask + scale + online softmax (each thread has full row)
        const int kbase = t * 64;
        float mloc = -1e30f;
#pragma unroll
        for (int j = 0; j < 64; j++) {
            s[j] = (kbase + j <= qi) ? s[j] * 0.125f : -1e30f;
            mloc = fmaxf(mloc, s[j]);
        }
        float mnew = fmaxf(m, mloc);
        float corr = __expf(m - mnew);
        float lloc = 0.f;
#pragma unroll
        for (int j = 0; j < 64; j++) {
            float p = __expf(s[j] - mnew);
            s[j] = p;
            lloc += p;
        }
        l = l * corr + lloc;
        m = mnew;
#pragma unroll
        for (int i = 0; i < 16; i++) o[i] *= corr;

        // o += P @ V  (this thread's 16 dims)
#pragma unroll
        for (int j = 0; j < 64; j++) {
            const float4* vp = (const float4*)&sV[j * 64 + tx * 16];
            float p = s[j];
#pragma unroll
            for (int i = 0; i < 4; i++) {
                float4 vv = vp[i];
                o[i * 4 + 0] += p * vv.x;
                o[i * 4 + 1] += p * vv.y;
                o[i * 4 + 2] += p * vv.z;
                o[i * 4 + 3] += p * vv.w;
            }
        }
    }

    float inv = 1.f / l;
    float* op = O + (size_t)(b * NSEQ + qi) * DMODEL + h * HD + tx * 16;
#pragma unroll
    for (int i = 0; i < 4; i++) {
        *(float4*)(op + i * 4) = make_float4(
            o[i * 4 + 0] * inv, o[i * 4 + 1] * inv,
            o[i * 4 + 2] * inv, o[i * 4 + 3] * inv);
    }
}

// ---------------------------------------------------------------------------
// Launch. Inputs (metadata order): x, Wq, Wk, Wv, Wo, freqs_cos, freqs_sin,
// attn_mask (ignored: causal is baked in). Output fp32 (B,N,D).
// ---------------------------------------------------------------------------
extern "C" void kernel_launch(void* const* d_in, const int* in_sizes, int n_in,
                              void* d_out, int out_size)
{
    const float* x  = (const float*)d_in[0];
    const float* Wq = (const float*)d_in[1];
    const float* Wk = (const float*)d_in[2];
    const float* Wv = (const float*)d_in[3];
    const float* Wo = (const float*)d_in[4];
    const float* fc = (const float*)d_in[5];
    const float* fs = (const float*)d_in[6];
    float* out = (float*)d_out;

    float *Qp, *Kp, *Vp, *Op;
    cudaGetSymbolAddress((void**)&Qp, g_Q);
    cudaGetSymbolAddress((void**)&Kp, g_K);
    cudaGetSymbolAddress((void**)&Vp, g_V);
    cudaGetSymbolAddress((void**)&Op, g_O);

    dim3 blk(256);
    dim3 gq(DMODEL / 128, ROWS / 128);          // (16, 32)
    dim3 gkv((NKVH * HD) / 128, ROWS / 128);    // (4, 32)

    sgemm128<<<gq,  blk>>>(x, Wq, Qp, ROWS, DMODEL,    DMODEL);
    sgemm128<<<gkv, blk>>>(x, Wk, Kp, ROWS, NKVH * HD, DMODEL);
    sgemm128<<<gkv, blk>>>(x, Wv, Vp, ROWS, NKVH * HD, DMODEL);

    int totQ = ROWS * (DMODEL / 2);             // 4,194,304 pairs
    int totK = ROWS * ((NKVH * HD) / 2);        // 1,048,576 pairs
    rope_k<<<(totQ + 255) / 256, 256>>>(Qp, fc, fs, DMODEL,    totQ);
    rope_k<<<(totK + 255) / 256, 256>>>(Kp, fc, fs, NKVH * HD, totK);

    attn64<<<dim3(NSEQ / 64, NH, BATCH), 256>>>(Qp, Kp, Vp, Op);

    sgemm128<<<gq, blk>>>(Op, Wo, out, ROWS, DMODEL, DMODEL);
}

// round 2
// speedup vs baseline: 1.3200x; 1.3200x over previous
#include <cuda_runtime.h>
#include <math.h>
#include <stdint.h>

// Problem constants
#define BATCH 2
#define NSEQ  2048
#define DMODEL 2048
#define NH    32
#define NKVH  8
#define HD    64
#define GRP   4          // NH / NKVH
#define ROWS  4096       // BATCH * NSEQ

// ---------------------------------------------------------------------------
// Scratch (device globals -- no allocation allowed anywhere)
// ---------------------------------------------------------------------------
__device__ float g_Q[(size_t)ROWS * DMODEL];          // 32 MB  (B*N, H*HD)
__device__ float g_K[(size_t)ROWS * (NKVH * HD)];     //  8 MB  (B*N, KVH*HD)
__device__ float g_V[(size_t)ROWS * (NKVH * HD)];     //  8 MB
__device__ float g_O[(size_t)ROWS * DMODEL];          // 32 MB  attention output

// ---------------------------------------------------------------------------
// Helpers: cp.async, tf32 convert, mma
// ---------------------------------------------------------------------------
__device__ __forceinline__ void cp_async16(void* smem, const void* gmem) {
    uint32_t s = (uint32_t)__cvta_generic_to_shared(smem);
    asm volatile("cp.async.cg.shared.global [%0], [%1], 16;\n" ::"r"(s), "l"(gmem));
}
#define CP_COMMIT() asm volatile("cp.async.commit_group;\n" ::: "memory")
#define CP_WAIT0()  asm volatile("cp.async.wait_group 0;\n" ::: "memory")

__device__ __forceinline__ uint32_t f2tf32(float x) {
    uint32_t r;
    asm("cvt.rna.tf32.f32 %0, %1;" : "=r"(r) : "f"(x));
    return r;
}

__device__ __forceinline__ void mma_tf32(float* c, const uint32_t* a, const uint32_t* b) {
    asm volatile(
        "mma.sync.aligned.m16n8k8.row.col.f32.tf32.tf32.f32 "
        "{%0,%1,%2,%3}, {%4,%5,%6,%7}, {%8,%9}, {%0,%1,%2,%3};"
        : "+f"(c[0]), "+f"(c[1]), "+f"(c[2]), "+f"(c[3])
        : "r"(a[0]), "r"(a[1]), "r"(a[2]), "r"(a[3]), "r"(b[0]), "r"(b[1]));
}

// ---------------------------------------------------------------------------
// TF32 tensor-core GEMM: C[M,N] = A[M,K] @ B[K,N], row-major fp32 in/out.
// Block tile 128x128x16, 8 warps (4 m x 2 n), warp tile 32x64 (2x8 mma frags).
// 2-stage cp.async double buffering. Requires M%128==0, N%128==0, K%16==0.
// ---------------------------------------------------------------------------
#define APAD 20   // floats per A smem row  (m-major [m][k])
#define BPAD 136  // floats per B smem row  (k-major [k][n])

__global__ __launch_bounds__(256, 2) void tf32gemm(
    const float* __restrict__ A, const float* __restrict__ B,
    float* __restrict__ C, int M, int N, int K)
{
    __shared__ float As[2][128][APAD];
    __shared__ float Bs[2][16][BPAD];

    const int tid  = threadIdx.x;
    const int lane = tid & 31;
    const int wid  = tid >> 5;
    const int wm   = wid & 3;        // 0..3 -> 32-row slice
    const int wn   = wid >> 2;       // 0..1 -> 64-col slice
    const int gid  = lane >> 2;      // 0..7
    const int tig  = lane & 3;       // 0..3

    const float* Ab = A + (size_t)(blockIdx.y * 128) * K;
    const float* Bb = B + blockIdx.x * 128;

    // A loader: chunk c in [0,512): m=c>>2, kq=(c&3)*4  (16B each)
    const int am  = tid >> 2;
    const int akq = (tid & 3) << 2;
    // B loader: chunk c in [0,512): k=c>>5, nq=(c&31)*4
    const int bk  = tid >> 5;
    const int bnq = (tid & 31) << 2;

    float acc[2][8][4];
#pragma unroll
    for (int mt = 0; mt < 2; mt++)
#pragma unroll
        for (int nt = 0; nt < 8; nt++)
#pragma unroll
            for (int i = 0; i < 4; i++) acc[mt][nt][i] = 0.f;

    // prologue: stage 0
    {
        cp_async16(&As[0][am][akq],        Ab + (size_t)am * K + akq);
        cp_async16(&As[0][am + 64][akq],   Ab + (size_t)(am + 64) * K + akq);
        cp_async16(&Bs[0][bk][bnq],        Bb + (size_t)bk * N + bnq);
        cp_async16(&Bs[0][bk + 8][bnq],    Bb + (size_t)(bk + 8) * N + bnq);
        CP_COMMIT();
    }

    const int nk = K / 16;
    for (int kt = 0; kt < nk; kt++) {
        CP_WAIT0();
        __syncthreads();
        const int st = kt & 1;

        if (kt + 1 < nk) {
            const int k0 = (kt + 1) * 16;
            cp_async16(&As[st ^ 1][am][akq],      Ab + (size_t)am * K + k0 + akq);
            cp_async16(&As[st ^ 1][am + 64][akq], Ab + (size_t)(am + 64) * K + k0 + akq);
            cp_async16(&Bs[st ^ 1][bk][bnq],      Bb + (size_t)(k0 + bk) * N + bnq);
            cp_async16(&Bs[st ^ 1][bk + 8][bnq],  Bb + (size_t)(k0 + bk + 8) * N + bnq);
            CP_COMMIT();
        }

#pragma unroll
        for (int ks = 0; ks < 2; ks++) {
            const int k0 = ks * 8;
            uint32_t a[2][4];
#pragma unroll
            for (int mt = 0; mt < 2; mt++) {
                const int mr = wm * 32 + mt * 16;
                a[mt][0] = f2tf32(As[st][mr + gid][k0 + tig]);
                a[mt][1] = f2tf32(As[st][mr + gid + 8][k0 + tig]);
                a[mt][2] = f2tf32(As[st][mr + gid][k0 + tig + 4]);
                a[mt][3] = f2tf32(As[st][mr + gid + 8][k0 + tig + 4]);
            }
            uint32_t b[8][2];
#pragma unroll
            for (int nt = 0; nt < 8; nt++) {
                const int nc = wn * 64 + nt * 8 + gid;
                b[nt][0] = f2tf32(Bs[st][k0 + tig][nc]);
                b[nt][1] = f2tf32(Bs[st][k0 + tig + 4][nc]);
            }
#pragma unroll
            for (int mt = 0; mt < 2; mt++)
#pragma unroll
                for (int nt = 0; nt < 8; nt++)
                    mma_tf32(acc[mt][nt], a[mt], b[nt]);
        }
    }

    // epilogue
    const int cm = blockIdx.y * 128 + wm * 32;
    const int cn = blockIdx.x * 128 + wn * 64;
#pragma unroll
    for (int mt = 0; mt < 2; mt++) {
#pragma unroll
        for (int nt = 0; nt < 8; nt++) {
            float* p0 = C + (size_t)(cm + mt * 16 + gid) * N + cn + nt * 8 + 2 * tig;
            float* p1 = p0 + (size_t)8 * N;
            *(float2*)p0 = make_float2(acc[mt][nt][0], acc[mt][nt][1]);
            *(float2*)p1 = make_float2(acc[mt][nt][2], acc[mt][nt][3]);
        }
    }
}

// ---------------------------------------------------------------------------
// RoPE (interleaved even/odd pairs), in place.
// ---------------------------------------------------------------------------
__global__ void rope_k(float* __restrict__ X,
                       const float* __restrict__ fc,
                       const float* __restrict__ fs,
                       int cols, int total)
{
    int idx = blockIdx.x * blockDim.x + threadIdx.x;
    if (idx >= total) return;
    const int half = cols >> 1;
    int row = idx / half;
    int c   = idx - row * half;
    int p   = c & 31;
    int n   = row & (NSEQ - 1);
    float cv = fc[n * 32 + p];
    float sv = fs[n * 32 + p];
    float2* ptr = (float2*)(X + (size_t)row * cols) + c;
    float2 x2 = *ptr;
    float2 r2;
    r2.x = x2.x * cv - x2.y * sv;
    r2.y = x2.x * sv + x2.y * cv;
    *ptr = r2;
}

// ---------------------------------------------------------------------------
// Flash attention, fp32, causal, GQA (unchanged from R1).
// ---------------------------------------------------------------------------
__global__ __launch_bounds__(256) void attn64(
    const float* __restrict__ Q, const float* __restrict__ Kg,
    const float* __restrict__ Vg, float* __restrict__ O)
{
    __shared__ float sK[64 * 64];
    __shared__ float sV[64 * 64];

    const int qt = blockIdx.x, h = blockIdx.y, b = blockIdx.z;
    const int kvh = h >> 2;
    const int tid = threadIdx.x;
    const int row = tid >> 2;
    const int tx  = tid & 3;
    const int qi  = qt * 64 + row;

    float qv[16];
    {
        const float* qptr =
            Q + (size_t)(b * NSEQ + qi) * DMODEL + h * HD + tx * 16;
#pragma unroll
        for (int i = 0; i < 4; i++) {
            float4 t4 = *(const float4*)(qptr + i * 4);
            qv[i * 4 + 0] = t4.x; qv[i * 4 + 1] = t4.y;
            qv[i * 4 + 2] = t4.z; qv[i * 4 + 3] = t4.w;
        }
    }

    float o[16];
#pragma unroll
    for (int i = 0; i < 16; i++) o[i] = 0.f;
    float m = -1e30f, l = 0.f;

    const int nT = qt + 1;
    for (int t = 0; t < nT; t++) {
        __syncthreads();
        {
            const float* kb =
                Kg + (size_t)(b * NSEQ + t * 64) * (NKVH * HD) + kvh * HD;
            const float* vb =
                Vg + (size_t)(b * NSEQ + t * 64) * (NKVH * HD) + kvh * HD;
#pragma unroll
            for (int i = 0; i < 4; i++) {
                int idx = tid + i * 256;
                int r = idx >> 4;
                int c = (idx & 15) << 2;
                *(float4*)&sK[r * 64 + c] =
                    *(const float4*)(kb + (size_t)r * (NKVH * HD) + c);
                *(float4*)&sV[r * 64 + c] =
                    *(const float4*)(vb + (size_t)r * (NKVH * HD) + c);
            }
        }
        __syncthreads();

        float s[64];
#pragma unroll
        for (int j = 0; j < 64; j++) {
            const float4* kp = (const float4*)&sK[j * 64 + tx * 16];
            float acc2 = 0.f;
#pragma unroll
            for (int i = 0; i < 4; i++) {
                float4 kk = kp[i];
                acc2 += qv[i * 4 + 0] * kk.x + qv[i * 4 + 1] * kk.y +
                        qv[i * 4 + 2] * kk.z + qv[i * 4 + 3] * kk.w;
            }
            s[j] = acc2;
        }
#pragma unroll
        for (int j = 0; j < 64; j++) {
            s[j] += __shfl_xor_sync(0xffffffffu, s[j], 1);
            s[j] += __shfl_xor_sync(0xffffffffu, s[j], 2);
        }

        const int kbase = t * 64;
        float mloc = -1e30f;
#pragma unroll
        for (int j = 0; j < 64; j++) {
            s[j] = (kbase + j <= qi) ? s[j] * 0.125f : -1e30f;
            mloc = fmaxf(mloc, s[j]);
        }
        float mnew = fmaxf(m, mloc);
        float corr = __expf(m - mnew);
        float lloc = 0.f;
#pragma unroll
        for (int j = 0; j < 64; j++) {
            float p = __expf(s[j] - mnew);
            s[j] = p;
            lloc += p;
        }
        l = l * corr + lloc;
        m = mnew;
#pragma unroll
        for (int i = 0; i < 16; i++) o[i] *= corr;

#pragma unroll
        for (int j = 0; j < 64; j++) {
            const float4* vp = (const float4*)&sV[j * 64 + tx * 16];
            float p = s[j];
#pragma unroll
            for (int i = 0; i < 4; i++) {
                float4 vv = vp[i];
                o[i * 4 + 0] += p * vv.x;
                o[i * 4 + 1] += p * vv.y;
                o[i * 4 + 2] += p * vv.z;
                o[i * 4 + 3] += p * vv.w;
            }
        }
    }

    float inv = 1.f / l;
    float* op = O + (size_t)(b * NSEQ + qi) * DMODEL + h * HD + tx * 16;
#pragma unroll
    for (int i = 0; i < 4; i++) {
        *(float4*)(op + i * 4) = make_float4(
            o[i * 4 + 0] * inv, o[i * 4 + 1] * inv,
            o[i * 4 + 2] * inv, o[i * 4 + 3] * inv);
    }
}

// ---------------------------------------------------------------------------
// Launch
// ---------------------------------------------------------------------------
extern "C" void kernel_launch(void* const* d_in, const int* in_sizes, int n_in,
                              void* d_out, int out_size)
{
    const float* x  = (const float*)d_in[0];
    const float* Wq = (const float*)d_in[1];
    const float* Wk = (const float*)d_in[2];
    const float* Wv = (const float*)d_in[3];
    const float* Wo = (const float*)d_in[4];
    const float* fc = (const float*)d_in[5];
    const float* fs = (const float*)d_in[6];
    float* out = (float*)d_out;

    float *Qp, *Kp, *Vp, *Op;
    cudaGetSymbolAddress((void**)&Qp, g_Q);
    cudaGetSymbolAddress((void**)&Kp, g_K);
    cudaGetSymbolAddress((void**)&Vp, g_V);
    cudaGetSymbolAddress((void**)&Op, g_O);

    dim3 blk(256);
    dim3 gq(DMODEL / 128, ROWS / 128);          // (16, 32)
    dim3 gkv((NKVH * HD) / 128, ROWS / 128);    // (4, 32)

    tf32gemm<<<gq,  blk>>>(x, Wq, Qp, ROWS, DMODEL,    DMODEL);
    tf32gemm<<<gkv, blk>>>(x, Wk, Kp, ROWS, NKVH * HD, DMODEL);
    tf32gemm<<<gkv, blk>>>(x, Wv, Vp, ROWS, NKVH * HD, DMODEL);

    int totQ = ROWS * (DMODEL / 2);
    int totK = ROWS * ((NKVH * HD) / 2);
    rope_k<<<(totQ + 255) / 256, 256>>>(Qp, fc, fs, DMODEL,    totQ);
    rope_k<<<(totK + 255) / 256, 256>>>(Kp, fc, fs, NKVH * HD, totK);

    attn64<<<dim3(NSEQ / 64, NH, BATCH), 256>>>(Qp, Kp, Vp, Op);

    tf32gemm<<<gq, blk>>>(Op, Wo, out, ROWS, DMODEL, DMODEL);
}

// round 3
// speedup vs baseline: 6.1402x; 4.6517x over previous
#include <cuda_runtime.h>
#include <math.h>
#include <stdint.h>

// Problem constants
#define BATCH 2
#define NSEQ  2048
#define DMODEL 2048
#define NH    32
#define NKVH  8
#define HD    64
#define GRP   4          // NH / NKVH
#define ROWS  4096       // BATCH * NSEQ

// ---------------------------------------------------------------------------
// Scratch (device globals -- no allocation allowed anywhere)
// ---------------------------------------------------------------------------
__device__ float g_Q[(size_t)ROWS * DMODEL];          // 32 MB
__device__ float g_K[(size_t)ROWS * (NKVH * HD)];     //  8 MB
__device__ float g_V[(size_t)ROWS * (NKVH * HD)];     //  8 MB
__device__ float g_O[(size_t)ROWS * DMODEL];          // 32 MB

// ---------------------------------------------------------------------------
// Helpers
// ---------------------------------------------------------------------------
__device__ __forceinline__ void cp_async16(void* smem, const void* gmem) {
    uint32_t s = (uint32_t)__cvta_generic_to_shared(smem);
    asm volatile("cp.async.cg.shared.global [%0], [%1], 16;\n" ::"r"(s), "l"(gmem));
}
#define CP_COMMIT() asm volatile("cp.async.commit_group;\n" ::: "memory")

__device__ __forceinline__ uint32_t f2tf32(float x) {
    uint32_t r;
    asm("cvt.rna.tf32.f32 %0, %1;" : "=r"(r) : "f"(x));
    return r;
}

__device__ __forceinline__ void mma_tf32(float* c, const uint32_t* a, const uint32_t* b) {
    asm volatile(
        "mma.sync.aligned.m16n8k8.row.col.f32.tf32.tf32.f32 "
        "{%0,%1,%2,%3}, {%4,%5,%6,%7}, {%8,%9}, {%0,%1,%2,%3};"
        : "+f"(c[0]), "+f"(c[1]), "+f"(c[2]), "+f"(c[3])
        : "r"(a[0]), "r"(a[1]), "r"(a[2]), "r"(a[3]), "r"(b[0]), "r"(b[1]));
}

// ---------------------------------------------------------------------------
// TF32 tensor-core GEMM (unchanged from R2)
// ---------------------------------------------------------------------------
#define APAD 20
#define BPAD 136

__global__ __launch_bounds__(256, 2) void tf32gemm(
    const float* __restrict__ A, const float* __restrict__ B,
    float* __restrict__ C, int M, int N, int K)
{
    __shared__ float As[2][128][APAD];
    __shared__ float Bs[2][16][BPAD];

    const int tid  = threadIdx.x;
    const int lane = tid & 31;
    const int wid  = tid >> 5;
    const int wm   = wid & 3;
    const int wn   = wid >> 2;
    const int gid  = lane >> 2;
    const int tig  = lane & 3;

    const float* Ab = A + (size_t)(blockIdx.y * 128) * K;
    const float* Bb = B + blockIdx.x * 128;

    const int am  = tid >> 2;
    const int akq = (tid & 3) << 2;
    const int bk  = tid >> 5;
    const int bnq = (tid & 31) << 2;

    float acc[2][8][4];
#pragma unroll
    for (int mt = 0; mt < 2; mt++)
#pragma unroll
        for (int nt = 0; nt < 8; nt++)
#pragma unroll
            for (int i = 0; i < 4; i++) acc[mt][nt][i] = 0.f;

    {
        cp_async16(&As[0][am][akq],        Ab + (size_t)am * K + akq);
        cp_async16(&As[0][am + 64][akq],   Ab + (size_t)(am + 64) * K + akq);
        cp_async16(&Bs[0][bk][bnq],        Bb + (size_t)bk * N + bnq);
        cp_async16(&Bs[0][bk + 8][bnq],    Bb + (size_t)(bk + 8) * N + bnq);
        CP_COMMIT();
    }

    const int nk = K / 16;
    for (int kt = 0; kt < nk; kt++) {
        asm volatile("cp.async.wait_group 0;\n" ::: "memory");
        __syncthreads();
        const int st = kt & 1;

        if (kt + 1 < nk) {
            const int k0 = (kt + 1) * 16;
            cp_async16(&As[st ^ 1][am][akq],      Ab + (size_t)am * K + k0 + akq);
            cp_async16(&As[st ^ 1][am + 64][akq], Ab + (size_t)(am + 64) * K + k0 + akq);
            cp_async16(&Bs[st ^ 1][bk][bnq],      Bb + (size_t)(k0 + bk) * N + bnq);
            cp_async16(&Bs[st ^ 1][bk + 8][bnq],  Bb + (size_t)(k0 + bk + 8) * N + bnq);
            CP_COMMIT();
        }

#pragma unroll
        for (int ks = 0; ks < 2; ks++) {
            const int k0 = ks * 8;
            uint32_t a[2][4];
#pragma unroll
            for (int mt = 0; mt < 2; mt++) {
                const int mr = wm * 32 + mt * 16;
                a[mt][0] = f2tf32(As[st][mr + gid][k0 + tig]);
                a[mt][1] = f2tf32(As[st][mr + gid + 8][k0 + tig]);
                a[mt][2] = f2tf32(As[st][mr + gid][k0 + tig + 4]);
                a[mt][3] = f2tf32(As[st][mr + gid + 8][k0 + tig + 4]);
            }
            uint32_t b[8][2];
#pragma unroll
            for (int nt = 0; nt < 8; nt++) {
                const int nc = wn * 64 + nt * 8 + gid;
                b[nt][0] = f2tf32(Bs[st][k0 + tig][nc]);
                b[nt][1] = f2tf32(Bs[st][k0 + tig + 4][nc]);
            }
#pragma unroll
            for (int mt = 0; mt < 2; mt++)
#pragma unroll
                for (int nt = 0; nt < 8; nt++)
                    mma_tf32(acc[mt][nt], a[mt], b[nt]);
        }
    }

    const int cm = blockIdx.y * 128 + wm * 32;
    const int cn = blockIdx.x * 128 + wn * 64;
#pragma unroll
    for (int mt = 0; mt < 2; mt++) {
#pragma unroll
        for (int nt = 0; nt < 8; nt++) {
            float* p0 = C + (size_t)(cm + mt * 16 + gid) * N + cn + nt * 8 + 2 * tig;
            float* p1 = p0 + (size_t)8 * N;
            *(float2*)p0 = make_float2(acc[mt][nt][0], acc[mt][nt][1]);
            *(float2*)p1 = make_float2(acc[mt][nt][2], acc[mt][nt][3]);
        }
    }
}

// ---------------------------------------------------------------------------
// RoPE (unchanged)
// ---------------------------------------------------------------------------
__global__ void rope_k(float* __restrict__ X,
                       const float* __restrict__ fc,
                       const float* __restrict__ fs,
                       int cols, int total)
{
    int idx = blockIdx.x * blockDim.x + threadIdx.x;
    if (idx >= total) return;
    const int half = cols >> 1;
    int row = idx / half;
    int c   = idx - row * half;
    int p   = c & 31;
    int n   = row & (NSEQ - 1);
    float cv = fc[n * 32 + p];
    float sv = fs[n * 32 + p];
    float2* ptr = (float2*)(X + (size_t)row * cols) + c;
    float2 x2 = *ptr;
    float2 r2;
    r2.x = x2.x * cv - x2.y * sv;
    r2.y = x2.x * sv + x2.y * cv;
    *ptr = r2;
}

// ---------------------------------------------------------------------------
// Tensor-core flash attention (tf32), causal, GQA.
// 128 threads = 4 warps; each warp owns 16 q rows of a 64-row q-block.
// K/V 64x64 tiles double-buffered via cp.async; Q fragments register-resident.
// Pitches: sK 68 floats, sV 72, sP 68 -- all fragment loads bank-conflict-free.
// ---------------------------------------------------------------------------
#define KPITCH 68
#define VPITCH 72
#define PPITCH 68
#define KBUF (64 * KPITCH)      // floats per K stage
#define VBUF (64 * VPITCH)
#define SMEM_ATTN ((2 * KBUF + 2 * VBUF + 4 * 16 * PPITCH) * 4)

__global__ __launch_bounds__(128) void attn_tc(
    const float* __restrict__ Q, const float* __restrict__ Kg,
    const float* __restrict__ Vg, float* __restrict__ O)
{
    extern __shared__ char smem_raw[];
    float*    sK = (float*)smem_raw;                           // [2][64][68]
    float*    sV = (float*)(smem_raw + 2 * KBUF * 4);          // [2][64][72]
    uint32_t* sP = (uint32_t*)(smem_raw + (2 * KBUF + 2 * VBUF) * 4); // [4][16][68]

    const int qt = blockIdx.x, h = blockIdx.y, b = blockIdx.z;
    const int kvh = h >> 2;
    const int tid = threadIdx.x;
    const int w = tid >> 5;
    const int lane = tid & 31;
    const int gid = lane >> 2, tig = lane & 3;

    const int qr0 = qt * 64 + w * 16 + gid;   // rows this thread's frags touch
    const int qr1 = qr0 + 8;

    // Q fragments: pre-scaled by 1/sqrt(HD), converted to tf32 once.
    uint32_t aq[8][4];
    {
        const float* q0 = Q + ((size_t)(b * NSEQ) + qr0) * DMODEL + h * HD;
        const float* q1 = Q + ((size_t)(b * NSEQ) + qr1) * DMODEL + h * HD;
#pragma unroll
        for (int ks = 0; ks < 8; ks++) {
            int d = ks * 8 + tig;
            aq[ks][0] = f2tf32(q0[d] * 0.125f);
            aq[ks][1] = f2tf32(q1[d] * 0.125f);
            aq[ks][2] = f2tf32(q0[d + 4] * 0.125f);
            aq[ks][3] = f2tf32(q1[d + 4] * 0.125f);
        }
    }

    float o[8][4];
#pragma unroll
    for (int nt = 0; nt < 8; nt++)
#pragma unroll
        for (int i = 0; i < 4; i++) o[nt][i] = 0.f;
    float m0 = -1e30f, l0 = 0.f, m1 = -1e30f, l1 = 0.f;

    const size_t kvs = NKVH * HD;   // 512

    // tile loader: K/V 64x64 via cp.async (8 chunks of 16B each per array)
    auto load_tile = [&](int t, int st) {
        const float* kb = Kg + (size_t)(b * NSEQ + t * 64) * kvs + kvh * HD;
        const float* vb = Vg + (size_t)(b * NSEQ + t * 64) * kvs + kvh * HD;
        float* dK = sK + st * KBUF;
        float* dV = sV + st * VBUF;
#pragma unroll
        for (int i = 0; i < 8; i++) {
            int c = tid + i * 128;
            int r = c >> 4, c4 = (c & 15) << 2;
            cp_async16(dK + r * KPITCH + c4, kb + (size_t)r * kvs + c4);
            cp_async16(dV + r * VPITCH + c4, vb + (size_t)r * kvs + c4);
        }
    };

    load_tile(0, 0);
    CP_COMMIT();

    for (int t = 0; t <= qt; t++) {
        const int st = t & 1;
        asm volatile("cp.async.wait_group 0;\n" ::: "memory");
        __syncthreads();   // tile t resident in all lanes' view; prev compute done

        if (t < qt) { load_tile(t + 1, st ^ 1); CP_COMMIT(); }

        const float* bK = sK + st * KBUF;
        const float* bV = sV + st * VBUF;

        // S = Q K^T (scaled). B-frag: b[r] = K[key = nt*8+gid][d = ks*8+tig+4r]
        float s[8][4];
#pragma unroll
        for (int nt = 0; nt < 8; nt++)
#pragma unroll
            for (int i = 0; i < 4; i++) s[nt][i] = 0.f;
#pragma unroll
        for (int ks = 0; ks < 8; ks++) {
            const int d0 = ks * 8;
#pragma unroll
            for (int nt = 0; nt < 8; nt++) {
                const float* kr = bK + (nt * 8 + gid) * KPITCH + d0 + tig;
                uint32_t bb[2];
                bb[0] = f2tf32(kr[0]);
                bb[1] = f2tf32(kr[4]);
                mma_tf32(s[nt], aq[ks], bb);
            }
        }

        // causal mask (only the diagonal tile needs it)
        if (t == qt) {
#pragma unroll
            for (int nt = 0; nt < 8; nt++) {
                int k0 = nt * 8 + 2 * tig;       // key offset within tile
                int r0 = w * 16 + gid;           // row offset within tile
                if (k0 > r0)     s[nt][0] = -1e30f;
                if (k0 + 1 > r0) s[nt][1] = -1e30f;
                if (k0 > r0 + 8)     s[nt][2] = -1e30f;
                if (k0 + 1 > r0 + 8) s[nt][3] = -1e30f;
            }
        }

        // online softmax: row0 = vals {s[nt][0],s[nt][1]}, row1 = {s[nt][2],s[nt][3]}
        float mx0 = -1e30f, mx1 = -1e30f;
#pragma unroll
        for (int nt = 0; nt < 8; nt++) {
            mx0 = fmaxf(mx0, fmaxf(s[nt][0], s[nt][1]));
            mx1 = fmaxf(mx1, fmaxf(s[nt][2], s[nt][3]));
        }
        mx0 = fmaxf(mx0, __shfl_xor_sync(0xffffffffu, mx0, 1));
        mx0 = fmaxf(mx0, __shfl_xor_sync(0xffffffffu, mx0, 2));
        mx1 = fmaxf(mx1, __shfl_xor_sync(0xffffffffu, mx1, 1));
        mx1 = fmaxf(mx1, __shfl_xor_sync(0xffffffffu, mx1, 2));

        float mn0 = fmaxf(m0, mx0), mn1 = fmaxf(m1, mx1);
        float c0 = __expf(m0 - mn0), c1 = __expf(m1 - mn1);
        float ls0 = 0.f, ls1 = 0.f;
#pragma unroll
        for (int nt = 0; nt < 8; nt++) {
            s[nt][0] = __expf(s[nt][0] - mn0);
            s[nt][1] = __expf(s[nt][1] - mn0);
            s[nt][2] = __expf(s[nt][2] - mn1);
            s[nt][3] = __expf(s[nt][3] - mn1);
            ls0 += s[nt][0] + s[nt][1];
            ls1 += s[nt][2] + s[nt][3];
        }
        ls0 += __shfl_xor_sync(0xffffffffu, ls0, 1);
        ls0 += __shfl_xor_sync(0xffffffffu, ls0, 2);
        ls1 += __shfl_xor_sync(0xffffffffu, ls1, 1);
        ls1 += __shfl_xor_sync(0xffffffffu, ls1, 2);
        l0 = l0 * c0 + ls0;
        l1 = l1 * c1 + ls1;
        m0 = mn0; m1 = mn1;
#pragma unroll
        for (int nt = 0; nt < 8; nt++) {
            o[nt][0] *= c0; o[nt][1] *= c0;
            o[nt][2] *= c1; o[nt][3] *= c1;
        }

        // P -> per-warp smem slice (tf32 bits), then reload as A-fragments
        uint32_t* pw = sP + w * (16 * PPITCH);
#pragma unroll
        for (int nt = 0; nt < 8; nt++) {
            uint2 v0 = make_uint2(f2tf32(s[nt][0]), f2tf32(s[nt][1]));
            uint2 v1 = make_uint2(f2tf32(s[nt][2]), f2tf32(s[nt][3]));
            *(uint2*)(pw + gid * PPITCH + nt * 8 + 2 * tig) = v0;
            *(uint2*)(pw + (gid + 8) * PPITCH + nt * 8 + 2 * tig) = v1;
        }
        __syncwarp();

        // O += P @ V.  B-frag: b[r] = V[key = ks*8+tig+4r][d = nt*8+gid]
#pragma unroll
        for (int ks = 0; ks < 8; ks++) {
            const int k0 = ks * 8;
            uint32_t ap[4];
            ap[0] = pw[gid * PPITCH + k0 + tig];
            ap[1] = pw[(gid + 8) * PPITCH + k0 + tig];
            ap[2] = pw[gid * PPITCH + k0 + tig + 4];
            ap[3] = pw[(gid + 8) * PPITCH + k0 + tig + 4];
#pragma unroll
            for (int nt = 0; nt < 8; nt++) {
                const float* vr = bV + (k0 + tig) * VPITCH + nt * 8 + gid;
                uint32_t bb[2];
                bb[0] = f2tf32(vr[0]);
                bb[1] = f2tf32(vr[4 * VPITCH]);
                mma_tf32(o[nt], ap, bb);
            }
        }
    }

    // epilogue: normalize and store
    float inv0 = 1.f / l0, inv1 = 1.f / l1;
    float* o0 = O + ((size_t)(b * NSEQ) + qr0) * DMODEL + h * HD;
    float* o1 = O + ((size_t)(b * NSEQ) + qr1) * DMODEL + h * HD;
#pragma unroll
    for (int nt = 0; nt < 8; nt++) {
        *(float2*)(o0 + nt * 8 + 2 * tig) =
            make_float2(o[nt][0] * inv0, o[nt][1] * inv0);
        *(float2*)(o1 + nt * 8 + 2 * tig) =
            make_float2(o[nt][2] * inv1, o[nt][3] * inv1);
    }
}

// ---------------------------------------------------------------------------
// Launch
// ---------------------------------------------------------------------------
extern "C" void kernel_launch(void* const* d_in, const int* in_sizes, int n_in,
                              void* d_out, int out_size)
{
    const float* x  = (const float*)d_in[0];
    const float* Wq = (const float*)d_in[1];
    const float* Wk = (const float*)d_in[2];
    const float* Wv = (const float*)d_in[3];
    const float* Wo = (const float*)d_in[4];
    const float* fc = (const float*)d_in[5];
    const float* fs = (const float*)d_in[6];
    float* out = (float*)d_out;

    float *Qp, *Kp, *Vp, *Op;
    cudaGetSymbolAddress((void**)&Qp, g_Q);
    cudaGetSymbolAddress((void**)&Kp, g_K);
    cudaGetSymbolAddress((void**)&Vp, g_V);
    cudaGetSymbolAddress((void**)&Op, g_O);

    static bool attr_set = false;
    if (!attr_set) {
        cudaFuncSetAttribute(attn_tc,
            cudaFuncAttributeMaxDynamicSharedMemorySize, SMEM_ATTN);
        attr_set = true;
    }

    dim3 blk(256);
    dim3 gq(DMODEL / 128, ROWS / 128);          // (16, 32)
    dim3 gkv((NKVH * HD) / 128, ROWS / 128);    // (4, 32)

    tf32gemm<<<gq,  blk>>>(x, Wq, Qp, ROWS, DMODEL,    DMODEL);
    tf32gemm<<<gkv, blk>>>(x, Wk, Kp, ROWS, NKVH * HD, DMODEL);
    tf32gemm<<<gkv, blk>>>(x, Wv, Vp, ROWS, NKVH * HD, DMODEL);

    int totQ = ROWS * (DMODEL / 2);
    int totK = ROWS * ((NKVH * HD) / 2);
    rope_k<<<(totQ + 255) / 256, 256>>>(Qp, fc, fs, DMODEL,    totQ);
    rope_k<<<(totK + 255) / 256, 256>>>(Kp, fc, fs, NKVH * HD, totK);

    attn_tc<<<dim3(NSEQ / 64, NH, BATCH), 128, SMEM_ATTN>>>(Qp, Kp, Vp, Op);

    tf32gemm<<<gq, blk>>>(Op, Wo, out, ROWS, DMODEL, DMODEL);
}

// round 6
// speedup vs baseline: 6.6866x; 1.0890x over previous
#include <cuda_runtime.h>
#include <math.h>
#include <stdint.h>

// Problem constants
#define BATCH 2
#define NSEQ  2048
#define DMODEL 2048
#define NH    32
#define NKVH  8
#define HD    64
#define ROWS  4096       // BATCH * NSEQ

// ---------------------------------------------------------------------------
// Scratch (device globals -- no allocation allowed anywhere)
// ---------------------------------------------------------------------------
__device__ float g_Q[(size_t)ROWS * DMODEL];
__device__ float g_K[(size_t)ROWS * (NKVH * HD)];
__device__ float g_V[(size_t)ROWS * (NKVH * HD)];
__device__ float g_O[(size_t)ROWS * DMODEL];
__device__ float g_xr[(size_t)ROWS * DMODEL];            // tf32-rounded x
__device__ float g_Wqr[(size_t)DMODEL * DMODEL];         // tf32-rounded weights
__device__ float g_Wkr[(size_t)DMODEL * (NKVH * HD)];
__device__ float g_Wvr[(size_t)DMODEL * (NKVH * HD)];
__device__ float g_Wor[(size_t)DMODEL * DMODEL];

// ---------------------------------------------------------------------------
// Helpers
// ---------------------------------------------------------------------------
__device__ __forceinline__ void cp_async16(void* smem, const void* gmem) {
    uint32_t s = (uint32_t)__cvta_generic_to_shared(smem);
    asm volatile("cp.async.cg.shared.global [%0], [%1], 16;\n" ::"r"(s), "l"(gmem));
}
#define CP_COMMIT() asm volatile("cp.async.commit_group;\n" ::: "memory")
#define CP_WAIT0()  asm volatile("cp.async.wait_group 0;\n" ::: "memory")

__device__ __forceinline__ uint32_t f2tf32(float x) {
    uint32_t r;
    asm("cvt.rna.tf32.f32 %0, %1;" : "=r"(r) : "f"(x));
    return r;
}
__device__ __forceinline__ float roundtf(float x) {
    return __uint_as_float(f2tf32(x));
}

__device__ __forceinline__ void mma_tf32(float* c, const uint32_t* a, const uint32_t* b) {
    asm volatile(
        "mma.sync.aligned.m16n8k8.row.col.f32.tf32.tf32.f32 "
        "{%0,%1,%2,%3}, {%4,%5,%6,%7}, {%8,%9}, {%0,%1,%2,%3};"
        : "+f"(c[0]), "+f"(c[1]), "+f"(c[2]), "+f"(c[3])
        : "r"(a[0]), "r"(a[1]), "r"(a[2]), "r"(a[3]), "r"(b[0]), "r"(b[1]));
}

// ---------------------------------------------------------------------------
// Fused tf32 rounding of x and all weights (one launch).
// Regions (in float4 units): xr, Wq, Wk, Wv, Wo.
// ---------------------------------------------------------------------------
#define N4_X   ((ROWS * DMODEL) / 4)                    // 2097152
#define N4_WQ  ((DMODEL * DMODEL) / 4)                  // 1048576
#define N4_WKV ((DMODEL * NKVH * HD) / 4)               // 262144
#define N4_ALL (N4_X + N4_WQ + 2 * N4_WKV + N4_WQ)      // 4718080

__global__ void round_all(const float4* __restrict__ x,
                          const float4* __restrict__ Wq,
                          const float4* __restrict__ Wk,
                          const float4* __restrict__ Wv,
                          const float4* __restrict__ Wo,
                          float4* __restrict__ xr,
                          float4* __restrict__ Wqr,
                          float4* __restrict__ Wkr,
                          float4* __restrict__ Wvr,
                          float4* __restrict__ Wor)
{
    int i = blockIdx.x * blockDim.x + threadIdx.x;
    if (i >= N4_ALL) return;
    const float4* src;
    float4* dst;
    int j = i;
    if (j < N4_X) { src = x; dst = xr; }
    else {
        j -= N4_X;
        if (j < N4_WQ) { src = Wq; dst = Wqr; }
        else {
            j -= N4_WQ;
            if (j < N4_WKV) { src = Wk; dst = Wkr; }
            else {
                j -= N4_WKV;
                if (j < N4_WKV) { src = Wv; dst = Wvr; }
                else { j -= N4_WKV; src = Wo; dst = Wor; }
            }
        }
    }
    float4 v = src[j];
    dst[j] = make_float4(roundtf(v.x), roundtf(v.y), roundtf(v.z), roundtf(v.w));
}

// ---------------------------------------------------------------------------
// TF32 tensor-core GEMM: C[M,N] = A[M,K] @ B[K,N], row-major fp32 in/out.
// Inputs are pre-rounded to tf32 -> fragment loads are raw bit loads (no CVT).
// Block tile 128x128x16, 8 warps (4m x 2n), warp tile 32x64.
// 2-stage cp.async double buffering.
// ---------------------------------------------------------------------------
#define APAD 20
#define BPAD 136

__global__ __launch_bounds__(256, 2) void tf32gemm(
    const float* __restrict__ A, const float* __restrict__ B,
    float* __restrict__ C, int M, int N, int K, int doRound)
{
    __shared__ float As[2][128][APAD];
    __shared__ float Bs[2][16][BPAD];

    const int tid  = threadIdx.x;
    const int lane = tid & 31;
    const int wid  = tid >> 5;
    const int wm   = wid & 3;
    const int wn   = wid >> 2;
    const int gid  = lane >> 2;
    const int tig  = lane & 3;

    const float* Ab = A + (size_t)(blockIdx.y * 128) * K;
    const float* Bb = B + blockIdx.x * 128;

    const int am  = tid >> 2;
    const int akq = (tid & 3) << 2;
    const int bk  = tid >> 5;
    const int bnq = (tid & 31) << 2;

    float acc[2][8][4];
#pragma unroll
    for (int mt = 0; mt < 2; mt++)
#pragma unroll
        for (int nt = 0; nt < 8; nt++)
#pragma unroll
            for (int i = 0; i < 4; i++) acc[mt][nt][i] = 0.f;

    {
        cp_async16(&As[0][am][akq],        Ab + (size_t)am * K + akq);
        cp_async16(&As[0][am + 64][akq],   Ab + (size_t)(am + 64) * K + akq);
        cp_async16(&Bs[0][bk][bnq],        Bb + (size_t)bk * N + bnq);
        cp_async16(&Bs[0][bk + 8][bnq],    Bb + (size_t)(bk + 8) * N + bnq);
        CP_COMMIT();
    }

    const int nk = K / 16;
    for (int kt = 0; kt < nk; kt++) {
        CP_WAIT0();
        __syncthreads();
        const int st = kt & 1;

        if (kt + 1 < nk) {
            const int k0 = (kt + 1) * 16;
            cp_async16(&As[st ^ 1][am][akq],      Ab + (size_t)am * K + k0 + akq);
            cp_async16(&As[st ^ 1][am + 64][akq], Ab + (size_t)(am + 64) * K + k0 + akq);
            cp_async16(&Bs[st ^ 1][bk][bnq],      Bb + (size_t)(k0 + bk) * N + bnq);
            cp_async16(&Bs[st ^ 1][bk + 8][bnq],  Bb + (size_t)(k0 + bk + 8) * N + bnq);
            CP_COMMIT();
        }

#pragma unroll
        for (int ks = 0; ks < 2; ks++) {
            const int k0 = ks * 8;
            uint32_t a[2][4];
#pragma unroll
            for (int mt = 0; mt < 2; mt++) {
                const int mr = wm * 32 + mt * 16;
                a[mt][0] = __float_as_uint(As[st][mr + gid][k0 + tig]);
                a[mt][1] = __float_as_uint(As[st][mr + gid + 8][k0 + tig]);
                a[mt][2] = __float_as_uint(As[st][mr + gid][k0 + tig + 4]);
                a[mt][3] = __float_as_uint(As[st][mr + gid + 8][k0 + tig + 4]);
            }
            uint32_t b[8][2];
#pragma unroll
            for (int nt = 0; nt < 8; nt++) {
                const int nc = wn * 64 + nt * 8 + gid;
                b[nt][0] = __float_as_uint(Bs[st][k0 + tig][nc]);
                b[nt][1] = __float_as_uint(Bs[st][k0 + tig + 4][nc]);
            }
#pragma unroll
            for (int mt = 0; mt < 2; mt++)
#pragma unroll
                for (int nt = 0; nt < 8; nt++)
                    mma_tf32(acc[mt][nt], a[mt], b[nt]);
        }
    }

    const int cm = blockIdx.y * 128 + wm * 32;
    const int cn = blockIdx.x * 128 + wn * 64;
#pragma unroll
    for (int mt = 0; mt < 2; mt++) {
#pragma unroll
        for (int nt = 0; nt < 8; nt++) {
            float* p0 = C + (size_t)(cm + mt * 16 + gid) * N + cn + nt * 8 + 2 * tig;
            float* p1 = p0 + (size_t)8 * N;
            if (doRound) {
                *(float2*)p0 = make_float2(roundtf(acc[mt][nt][0]), roundtf(acc[mt][nt][1]));
                *(float2*)p1 = make_float2(roundtf(acc[mt][nt][2]), roundtf(acc[mt][nt][3]));
            } else {
                *(float2*)p0 = make_float2(acc[mt][nt][0], acc[mt][nt][1]);
                *(float2*)p1 = make_float2(acc[mt][nt][2], acc[mt][nt][3]);
            }
        }
    }
}

// ---------------------------------------------------------------------------
// RoPE (interleaved pairs), in place, rounds outputs to tf32.
// ---------------------------------------------------------------------------
__global__ void rope_k(float* __restrict__ X,
                       const float* __restrict__ fc,
                       const float* __restrict__ fs,
                       int cols, int total)
{
    int idx = blockIdx.x * blockDim.x + threadIdx.x;
    if (idx >= total) return;
    const int half = cols >> 1;
    int row = idx / half;
    int c   = idx - row * half;
    int p   = c & 31;
    int n   = row & (NSEQ - 1);
    float cv = fc[n * 32 + p];
    float sv = fs[n * 32 + p];
    float2* ptr = (float2*)(X + (size_t)row * cols) + c;
    float2 x2 = *ptr;
    float2 r2;
    r2.x = roundtf(x2.x * cv - x2.y * sv);
    r2.y = roundtf(x2.x * sv + x2.y * cv);
    *ptr = r2;
}

// ---------------------------------------------------------------------------
// Tensor-core flash attention (tf32), causal, GQA. Inputs pre-rounded ->
// raw-bit fragment loads (no CVT). Output rounded for the O-projection.
// ---------------------------------------------------------------------------
#define KPITCH 68
#define VPITCH 72
#define PPITCH 68
#define KBUF (64 * KPITCH)
#define VBUF (64 * VPITCH)
#define SMEM_ATTN ((2 * KBUF + 2 * VBUF + 4 * 16 * PPITCH) * 4)

__global__ __launch_bounds__(128) void attn_tc(
    const float* __restrict__ Q, const float* __restrict__ Kg,
    const float* __restrict__ Vg, float* __restrict__ O)
{
    extern __shared__ char smem_raw[];
    float*    sK = (float*)smem_raw;
    float*    sV = (float*)(smem_raw + 2 * KBUF * 4);
    uint32_t* sP = (uint32_t*)(smem_raw + (2 * KBUF + 2 * VBUF) * 4);

    const int qt = blockIdx.x, h = blockIdx.y, b = blockIdx.z;
    const int kvh = h >> 2;
    const int tid = threadIdx.x;
    const int w = tid >> 5;
    const int lane = tid & 31;
    const int gid = lane >> 2, tig = lane & 3;

    const int qr0 = qt * 64 + w * 16 + gid;
    const int qr1 = qr0 + 8;

    uint32_t aq[8][4];
    {
        const float* q0 = Q + ((size_t)(b * NSEQ) + qr0) * DMODEL + h * HD;
        const float* q1 = Q + ((size_t)(b * NSEQ) + qr1) * DMODEL + h * HD;
#pragma unroll
        for (int ks = 0; ks < 8; ks++) {
            int d = ks * 8 + tig;
            aq[ks][0] = __float_as_uint(q0[d] * 0.125f);   // exact pow2 scale
            aq[ks][1] = __float_as_uint(q1[d] * 0.125f);
            aq[ks][2] = __float_as_uint(q0[d + 4] * 0.125f);
            aq[ks][3] = __float_as_uint(q1[d + 4] * 0.125f);
        }
    }

    float o[8][4];
#pragma unroll
    for (int nt = 0; nt < 8; nt++)
#pragma unroll
        for (int i = 0; i < 4; i++) o[nt][i] = 0.f;
    float m0 = -1e30f, l0 = 0.f, m1 = -1e30f, l1 = 0.f;

    const size_t kvs = NKVH * HD;

    auto load_tile = [&](int t, int st) {
        const float* kb = Kg + (size_t)(b * NSEQ + t * 64) * kvs + kvh * HD;
        const float* vb = Vg + (size_t)(b * NSEQ + t * 64) * kvs + kvh * HD;
        float* dK = sK + st * KBUF;
        float* dV = sV + st * VBUF;
#pragma unroll
        for (int i = 0; i < 8; i++) {
            int c = tid + i * 128;
            int r = c >> 4, c4 = (c & 15) << 2;
            cp_async16(dK + r * KPITCH + c4, kb + (size_t)r * kvs + c4);
            cp_async16(dV + r * VPITCH + c4, vb + (size_t)r * kvs + c4);
        }
    };

    load_tile(0, 0);
    CP_COMMIT();

    for (int t = 0; t <= qt; t++) {
        const int st = t & 1;
        CP_WAIT0();
        __syncthreads();

        if (t < qt) { load_tile(t + 1, st ^ 1); CP_COMMIT(); }

        const float* bK = sK + st * KBUF;
        const float* bV = sV + st * VBUF;

        float s[8][4];
#pragma unroll
        for (int nt = 0; nt < 8; nt++)
#pragma unroll
            for (int i = 0; i < 4; i++) s[nt][i] = 0.f;
#pragma unroll
        for (int ks = 0; ks < 8; ks++) {
            const int d0 = ks * 8;
#pragma unroll
            for (int nt = 0; nt < 8; nt++) {
                const float* kr = bK + (nt * 8 + gid) * KPITCH + d0 + tig;
                uint32_t bb[2];
                bb[0] = __float_as_uint(kr[0]);
                bb[1] = __float_as_uint(kr[4]);
                mma_tf32(s[nt], aq[ks], bb);
            }
        }

        if (t == qt) {
#pragma unroll
            for (int nt = 0; nt < 8; nt++) {
                int k0 = nt * 8 + 2 * tig;
                int r0 = w * 16 + gid;
                if (k0 > r0)         s[nt][0] = -1e30f;
                if (k0 + 1 > r0)     s[nt][1] = -1e30f;
                if (k0 > r0 + 8)     s[nt][2] = -1e30f;
                if (k0 + 1 > r0 + 8) s[nt][3] = -1e30f;
            }
        }

        float mx0 = -1e30f, mx1 = -1e30f;
#pragma unroll
        for (int nt = 0; nt < 8; nt++) {
            mx0 = fmaxf(mx0, fmaxf(s[nt][0], s[nt][1]));
            mx1 = fmaxf(mx1, fmaxf(s[nt][2], s[nt][3]));
        }
        mx0 = fmaxf(mx0, __shfl_xor_sync(0xffffffffu, mx0, 1));
        mx0 = fmaxf(mx0, __shfl_xor_sync(0xffffffffu, mx0, 2));
        mx1 = fmaxf(mx1, __shfl_xor_sync(0xffffffffu, mx1, 1));
        mx1 = fmaxf(mx1, __shfl_xor_sync(0xffffffffu, mx1, 2));

        float mn0 = fmaxf(m0, mx0), mn1 = fmaxf(m1, mx1);
        float c0 = __expf(m0 - mn0), c1 = __expf(m1 - mn1);
        float ls0 = 0.f, ls1 = 0.f;
#pragma unroll
        for (int nt = 0; nt < 8; nt++) {
            s[nt][0] = __expf(s[nt][0] - mn0);
            s[nt][1] = __expf(s[nt][1] - mn0);
            s[nt][2] = __expf(s[nt][2] - mn1);
            s[nt][3] = __expf(s[nt][3] - mn1);
            ls0 += s[nt][0] + s[nt][1];
            ls1 += s[nt][2] + s[nt][3];
        }
        ls0 += __shfl_xor_sync(0xffffffffu, ls0, 1);
        ls0 += __shfl_xor_sync(0xffffffffu, ls0, 2);
        ls1 += __shfl_xor_sync(0xffffffffu, ls1, 1);
        ls1 += __shfl_xor_sync(0xffffffffu, ls1, 2);
        l0 = l0 * c0 + ls0;
        l1 = l1 * c1 + ls1;
        m0 = mn0; m1 = mn1;
#pragma unroll
        for (int nt = 0; nt < 8; nt++) {
            o[nt][0] *= c0; o[nt][1] *= c0;
            o[nt][2] *= c1; o[nt][3] *= c1;
        }

        uint32_t* pw = sP + w * (16 * PPITCH);
#pragma unroll
        for (int nt = 0; nt < 8; nt++) {
            uint2 v0 = make_uint2(f2tf32(s[nt][0]), f2tf32(s[nt][1]));
            uint2 v1 = make_uint2(f2tf32(s[nt][2]), f2tf32(s[nt][3]));
            *(uint2*)(pw + gid * PPITCH + nt * 8 + 2 * tig) = v0;
            *(uint2*)(pw + (gid + 8) * PPITCH + nt * 8 + 2 * tig) = v1;
        }
        __syncwarp();

#pragma unroll
        for (int ks = 0; ks < 8; ks++) {
            const int k0 = ks * 8;
            uint32_t ap[4];
            ap[0] = pw[gid * PPITCH + k0 + tig];
            ap[1] = pw[(gid + 8) * PPITCH + k0 + tig];
            ap[2] = pw[gid * PPITCH + k0 + tig + 4];
            ap[3] = pw[(gid + 8) * PPITCH + k0 + tig + 4];
#pragma unroll
            for (int nt = 0; nt < 8; nt++) {
                const float* vr = bV + (k0 + tig) * VPITCH + nt * 8 + gid;
                uint32_t bb[2];
                bb[0] = __float_as_uint(vr[0]);
                bb[1] = __float_as_uint(vr[4 * VPITCH]);
                mma_tf32(o[nt], ap, bb);
            }
        }
    }

    float inv0 = 1.f / l0, inv1 = 1.f / l1;
    float* o0 = O + ((size_t)(b * NSEQ) + qr0) * DMODEL + h * HD;
    float* o1 = O + ((size_t)(b * NSEQ) + qr1) * DMODEL + h * HD;
#pragma unroll
    for (int nt = 0; nt < 8; nt++) {
        *(float2*)(o0 + nt * 8 + 2 * tig) =
            make_float2(roundtf(o[nt][0] * inv0), roundtf(o[nt][1] * inv0));
        *(float2*)(o1 + nt * 8 + 2 * tig) =
            make_float2(roundtf(o[nt][2] * inv1), roundtf(o[nt][3] * inv1));
    }
}

// ---------------------------------------------------------------------------
// Launch. Order chosen so the ncu-captured slot (#4) is the big Q GEMM.
// ---------------------------------------------------------------------------
extern "C" void kernel_launch(void* const* d_in, const int* in_sizes, int n_in,
                              void* d_out, int out_size)
{
    const float* x  = (const float*)d_in[0];
    const float* Wq = (const float*)d_in[1];
    const float* Wk = (const float*)d_in[2];
    const float* Wv = (const float*)d_in[3];
    const float* Wo = (const float*)d_in[4];
    const float* fc = (const float*)d_in[5];
    const float* fs = (const float*)d_in[6];
    float* out = (float*)d_out;

    float *Qp, *Kp, *Vp, *Op, *xr, *Wqr, *Wkr, *Wvr, *Wor;
    cudaGetSymbolAddress((void**)&Qp,  g_Q);
    cudaGetSymbolAddress((void**)&Kp,  g_K);
    cudaGetSymbolAddress((void**)&Vp,  g_V);
    cudaGetSymbolAddress((void**)&Op,  g_O);
    cudaGetSymbolAddress((void**)&xr,  g_xr);
    cudaGetSymbolAddress((void**)&Wqr, g_Wqr);
    cudaGetSymbolAddress((void**)&Wkr, g_Wkr);
    cudaGetSymbolAddress((void**)&Wvr, g_Wvr);
    cudaGetSymbolAddress((void**)&Wor, g_Wor);

    static bool attr_set = false;
    if (!attr_set) {
        cudaFuncSetAttribute(attn_tc,
            cudaFuncAttributeMaxDynamicSharedMemorySize, SMEM_ATTN);
        attr_set = true;
    }

    dim3 blk(256);
    dim3 gq(DMODEL / 128, ROWS / 128);          // (16, 32)
    dim3 gkv((NKVH * HD) / 128, ROWS / 128);    // (4, 32)

    // 1: fused tf32 rounding of x + all weights
    round_all<<<(N4_ALL + 255) / 256, 256>>>(
        (const float4*)x, (const float4*)Wq, (const float4*)Wk,
        (const float4*)Wv, (const float4*)Wo,
        (float4*)xr, (float4*)Wqr, (float4*)Wkr, (float4*)Wvr, (float4*)Wor);

    // 2,3: K and V projections (V rounded for attn raw loads)
    tf32gemm<<<gkv, blk>>>(xr, Wkr, Kp, ROWS, NKVH * HD, DMODEL, 0);
    tf32gemm<<<gkv, blk>>>(xr, Wvr, Vp, ROWS, NKVH * HD, DMODEL, 1);

    // 4: Q projection  <-- ncu capture slot
    tf32gemm<<<gq, blk>>>(xr, Wqr, Qp, ROWS, DMODEL, DMODEL, 0);

    // 5,6: RoPE (rounds outputs)
    int totQ = ROWS * (DMODEL / 2);
    int totK = ROWS * ((NKVH * HD) / 2);
    rope_k<<<(totQ + 255) / 256, 256>>>(Qp, fc, fs, DMODEL,    totQ);
    rope_k<<<(totK + 255) / 256, 256>>>(Kp, fc, fs, NKVH * HD, totK);

    // 7: attention
    attn_tc<<<dim3(NSEQ / 64, NH, BATCH), 128, SMEM_ATTN>>>(Qp, Kp, Vp, Op);

    // 8: output projection
    tf32gemm<<<gq, blk>>>(Op, Wor, out, ROWS, DMODEL, DMODEL, 0);
}

// round 7
// speedup vs baseline: 6.9166x; 1.0344x over previous
#include <cuda_runtime.h>
#include <math.h>
#include <stdint.h>

// Problem constants
#define BATCH 2
#define NSEQ  2048
#define DMODEL 2048
#define NH    32
#define NKVH  8
#define HD    64
#define ROWS  4096       // BATCH * NSEQ

// ---------------------------------------------------------------------------
// Scratch (device globals -- no allocation allowed anywhere)
// ---------------------------------------------------------------------------
__device__ float g_Q[(size_t)ROWS * DMODEL];
__device__ float g_K[(size_t)ROWS * (NKVH * HD)];
__device__ float g_V[(size_t)ROWS * (NKVH * HD)];
__device__ float g_O[(size_t)ROWS * DMODEL];
__device__ float g_xr[(size_t)ROWS * DMODEL];            // tf32-rounded x
__device__ float g_Wqr[(size_t)DMODEL * DMODEL];         // tf32-rounded weights
__device__ float g_Wkr[(size_t)DMODEL * (NKVH * HD)];
__device__ float g_Wvr[(size_t)DMODEL * (NKVH * HD)];
__device__ float g_Wor[(size_t)DMODEL * DMODEL];

// ---------------------------------------------------------------------------
// Helpers
// ---------------------------------------------------------------------------
__device__ __forceinline__ void cp_async16(void* smem, const void* gmem) {
    uint32_t s = (uint32_t)__cvta_generic_to_shared(smem);
    asm volatile("cp.async.cg.shared.global [%0], [%1], 16;\n" ::"r"(s), "l"(gmem));
}
#define CP_COMMIT() asm volatile("cp.async.commit_group;\n" ::: "memory")
#define CP_WAIT0()  asm volatile("cp.async.wait_group 0;\n" ::: "memory")

__device__ __forceinline__ uint32_t f2tf32(float x) {
    uint32_t r;
    asm("cvt.rna.tf32.f32 %0, %1;" : "=r"(r) : "f"(x));
    return r;
}
__device__ __forceinline__ float roundtf(float x) {
    return __uint_as_float(f2tf32(x));
}

__device__ __forceinline__ void mma_tf32(float* c, const uint32_t* a, const uint32_t* b) {
    asm volatile(
        "mma.sync.aligned.m16n8k8.row.col.f32.tf32.tf32.f32 "
        "{%0,%1,%2,%3}, {%4,%5,%6,%7}, {%8,%9}, {%0,%1,%2,%3};"
        : "+f"(c[0]), "+f"(c[1]), "+f"(c[2]), "+f"(c[3])
        : "r"(a[0]), "r"(a[1]), "r"(a[2]), "r"(a[3]), "r"(b[0]), "r"(b[1]));
}

// ---------------------------------------------------------------------------
// Prep: tf32-round x (launch 1) and all weights (launch 2)
// ---------------------------------------------------------------------------
#define N4_X   ((ROWS * DMODEL) / 4)
#define N4_WQ  ((DMODEL * DMODEL) / 4)
#define N4_WKV ((DMODEL * NKVH * HD) / 4)
#define N4_W_ALL (N4_WQ + 2 * N4_WKV + N4_WQ)

__global__ void round_x(const float4* __restrict__ x, float4* __restrict__ xr) {
    int i = blockIdx.x * blockDim.x + threadIdx.x;
    if (i >= N4_X) return;
    float4 v = x[i];
    xr[i] = make_float4(roundtf(v.x), roundtf(v.y), roundtf(v.z), roundtf(v.w));
}

__global__ void round_w(const float4* __restrict__ Wq,
                        const float4* __restrict__ Wk,
                        const float4* __restrict__ Wv,
                        const float4* __restrict__ Wo,
                        float4* __restrict__ Wqr,
                        float4* __restrict__ Wkr,
                        float4* __restrict__ Wvr,
                        float4* __restrict__ Wor)
{
    int i = blockIdx.x * blockDim.x + threadIdx.x;
    if (i >= N4_W_ALL) return;
    const float4* src;
    float4* dst;
    int j = i;
    if (j < N4_WQ) { src = Wq; dst = Wqr; }
    else {
        j -= N4_WQ;
        if (j < N4_WKV) { src = Wk; dst = Wkr; }
        else {
            j -= N4_WKV;
            if (j < N4_WKV) { src = Wv; dst = Wvr; }
            else { j -= N4_WKV; src = Wo; dst = Wor; }
        }
    }
    float4 v = src[j];
    dst[j] = make_float4(roundtf(v.x), roundtf(v.y), roundtf(v.z), roundtf(v.w));
}

// ---------------------------------------------------------------------------
// Shared GEMM mainloop (macro-free duplication kept readable):
// block tile 128x128x16, 8 warps (4m x 2n), 2-stage cp.async.
// ---------------------------------------------------------------------------
#define APAD 20
#define BPAD 136

// Fused QKV projection + RoPE epilogue.
// grid (24, 32): bx in [0,16) -> Q tile bx; [16,20) -> K tile bx-16; [20,24) -> V.
__global__ __launch_bounds__(256, 2) void qkv_gemm(
    const float* __restrict__ A,
    const float* __restrict__ Wq, const float* __restrict__ Wk,
    const float* __restrict__ Wv,
    float* __restrict__ Qo, float* __restrict__ Ko, float* __restrict__ Vo,
    const float* __restrict__ fc, const float* __restrict__ fs)
{
    __shared__ float As[2][128][APAD];
    __shared__ float Bs[2][16][BPAD];

    const int tid  = threadIdx.x;
    const int lane = tid & 31;
    const int wid  = tid >> 5;
    const int wm   = wid & 3;
    const int wn   = wid >> 2;
    const int gid  = lane >> 2;
    const int tig  = lane & 3;
    const int bx   = blockIdx.x;

    const float* B;
    float* C;
    int nTile, Ntot, doRope;
    if (bx < 16)      { B = Wq; C = Qo; nTile = bx;      Ntot = DMODEL;    doRope = 1; }
    else if (bx < 20) { B = Wk; C = Ko; nTile = bx - 16; Ntot = NKVH * HD; doRope = 1; }
    else              { B = Wv; C = Vo; nTile = bx - 20; Ntot = NKVH * HD; doRope = 0; }

    const int K = DMODEL;
    const float* Ab = A + (size_t)(blockIdx.y * 128) * K;
    const float* Bb = B + nTile * 128;

    const int am  = tid >> 2;
    const int akq = (tid & 3) << 2;
    const int bk  = tid >> 5;
    const int bnq = (tid & 31) << 2;

    float acc[2][8][4];
#pragma unroll
    for (int mt = 0; mt < 2; mt++)
#pragma unroll
        for (int nt = 0; nt < 8; nt++)
#pragma unroll
            for (int i = 0; i < 4; i++) acc[mt][nt][i] = 0.f;

    {
        cp_async16(&As[0][am][akq],        Ab + (size_t)am * K + akq);
        cp_async16(&As[0][am + 64][akq],   Ab + (size_t)(am + 64) * K + akq);
        cp_async16(&Bs[0][bk][bnq],        Bb + (size_t)bk * Ntot + bnq);
        cp_async16(&Bs[0][bk + 8][bnq],    Bb + (size_t)(bk + 8) * Ntot + bnq);
        CP_COMMIT();
    }

    const int nk = K / 16;
    for (int kt = 0; kt < nk; kt++) {
        CP_WAIT0();
        __syncthreads();
        const int st = kt & 1;

        if (kt + 1 < nk) {
            const int k0 = (kt + 1) * 16;
            cp_async16(&As[st ^ 1][am][akq],      Ab + (size_t)am * K + k0 + akq);
            cp_async16(&As[st ^ 1][am + 64][akq], Ab + (size_t)(am + 64) * K + k0 + akq);
            cp_async16(&Bs[st ^ 1][bk][bnq],      Bb + (size_t)(k0 + bk) * Ntot + bnq);
            cp_async16(&Bs[st ^ 1][bk + 8][bnq],  Bb + (size_t)(k0 + bk + 8) * Ntot + bnq);
            CP_COMMIT();
        }

#pragma unroll
        for (int ks = 0; ks < 2; ks++) {
            const int k0 = ks * 8;
            uint32_t a[2][4];
#pragma unroll
            for (int mt = 0; mt < 2; mt++) {
                const int mr = wm * 32 + mt * 16;
                a[mt][0] = __float_as_uint(As[st][mr + gid][k0 + tig]);
                a[mt][1] = __float_as_uint(As[st][mr + gid + 8][k0 + tig]);
                a[mt][2] = __float_as_uint(As[st][mr + gid][k0 + tig + 4]);
                a[mt][3] = __float_as_uint(As[st][mr + gid + 8][k0 + tig + 4]);
            }
            uint32_t b[8][2];
#pragma unroll
            for (int nt = 0; nt < 8; nt++) {
                const int nc = wn * 64 + nt * 8 + gid;
                b[nt][0] = __float_as_uint(Bs[st][k0 + tig][nc]);
                b[nt][1] = __float_as_uint(Bs[st][k0 + tig + 4][nc]);
            }
#pragma unroll
            for (int mt = 0; mt < 2; mt++)
#pragma unroll
                for (int nt = 0; nt < 8; nt++)
                    mma_tf32(acc[mt][nt], a[mt], b[nt]);
        }
    }

    // Epilogue: rows cm+mt*16+gid (+8), cols cn+nt*8+2tig (+1).
    // acc[..][0/1] = (even,odd) pair of row r0; acc[..][2/3] same for r0+8.
    const int cm = blockIdx.y * 128 + wm * 32;
    const int cn = nTile * 128 + wn * 64;
#pragma unroll
    for (int mt = 0; mt < 2; mt++) {
        const int r0 = cm + mt * 16 + gid;
        const int r1 = r0 + 8;
#pragma unroll
        for (int nt = 0; nt < 8; nt++) {
            const int col = cn + nt * 8 + 2 * tig;
            float* p0 = C + (size_t)r0 * Ntot + col;
            float* p1 = C + (size_t)r1 * Ntot + col;
            if (doRope) {
                const int p  = (col >> 1) & 31;        // pair index within head
                const int n0 = r0 & (NSEQ - 1);
                const int n1 = r1 & (NSEQ - 1);
                float c0 = fc[n0 * 32 + p], s0 = fs[n0 * 32 + p];
                float c1 = fc[n1 * 32 + p], s1 = fs[n1 * 32 + p];
                float xr0 = acc[mt][nt][0], xi0 = acc[mt][nt][1];
                float xr1 = acc[mt][nt][2], xi1 = acc[mt][nt][3];
                *(float2*)p0 = make_float2(roundtf(xr0 * c0 - xi0 * s0),
                                           roundtf(xr0 * s0 + xi0 * c0));
                *(float2*)p1 = make_float2(roundtf(xr1 * c1 - xi1 * s1),
                                           roundtf(xr1 * s1 + xi1 * c1));
            } else {
                *(float2*)p0 = make_float2(roundtf(acc[mt][nt][0]),
                                           roundtf(acc[mt][nt][1]));
                *(float2*)p1 = make_float2(roundtf(acc[mt][nt][2]),
                                           roundtf(acc[mt][nt][3]));
            }
        }
    }
}

// Plain GEMM for the output projection (no rounding of C).
__global__ __launch_bounds__(256, 2) void tf32gemm(
    const float* __restrict__ A, const float* __restrict__ B,
    float* __restrict__ C, int M, int N, int K)
{
    __shared__ float As[2][128][APAD];
    __shared__ float Bs[2][16][BPAD];

    const int tid  = threadIdx.x;
    const int lane = tid & 31;
    const int wid  = tid >> 5;
    const int wm   = wid & 3;
    const int wn   = wid >> 2;
    const int gid  = lane >> 2;
    const int tig  = lane & 3;

    const float* Ab = A + (size_t)(blockIdx.y * 128) * K;
    const float* Bb = B + blockIdx.x * 128;

    const int am  = tid >> 2;
    const int akq = (tid & 3) << 2;
    const int bk  = tid >> 5;
    const int bnq = (tid & 31) << 2;

    float acc[2][8][4];
#pragma unroll
    for (int mt = 0; mt < 2; mt++)
#pragma unroll
        for (int nt = 0; nt < 8; nt++)
#pragma unroll
            for (int i = 0; i < 4; i++) acc[mt][nt][i] = 0.f;

    {
        cp_async16(&As[0][am][akq],        Ab + (size_t)am * K + akq);
        cp_async16(&As[0][am + 64][akq],   Ab + (size_t)(am + 64) * K + akq);
        cp_async16(&Bs[0][bk][bnq],        Bb + (size_t)bk * N + bnq);
        cp_async16(&Bs[0][bk + 8][bnq],    Bb + (size_t)(bk + 8) * N + bnq);
        CP_COMMIT();
    }

    const int nk = K / 16;
    for (int kt = 0; kt < nk; kt++) {
        CP_WAIT0();
        __syncthreads();
        const int st = kt & 1;

        if (kt + 1 < nk) {
            const int k0 = (kt + 1) * 16;
            cp_async16(&As[st ^ 1][am][akq],      Ab + (size_t)am * K + k0 + akq);
            cp_async16(&As[st ^ 1][am + 64][akq], Ab + (size_t)(am + 64) * K + k0 + akq);
            cp_async16(&Bs[st ^ 1][bk][bnq],      Bb + (size_t)(k0 + bk) * N + bnq);
            cp_async16(&Bs[st ^ 1][bk + 8][bnq],  Bb + (size_t)(k0 + bk + 8) * N + bnq);
            CP_COMMIT();
        }

#pragma unroll
        for (int ks = 0; ks < 2; ks++) {
            const int k0 = ks * 8;
            uint32_t a[2][4];
#pragma unroll
            for (int mt = 0; mt < 2; mt++) {
                const int mr = wm * 32 + mt * 16;
                a[mt][0] = __float_as_uint(As[st][mr + gid][k0 + tig]);
                a[mt][1] = __float_as_uint(As[st][mr + gid + 8][k0 + tig]);
                a[mt][2] = __float_as_uint(As[st][mr + gid][k0 + tig + 4]);
                a[mt][3] = __float_as_uint(As[st][mr + gid + 8][k0 + tig + 4]);
            }
            uint32_t b[8][2];
#pragma unroll
            for (int nt = 0; nt < 8; nt++) {
                const int nc = wn * 64 + nt * 8 + gid;
                b[nt][0] = __float_as_uint(Bs[st][k0 + tig][nc]);
                b[nt][1] = __float_as_uint(Bs[st][k0 + tig + 4][nc]);
            }
#pragma unroll
            for (int mt = 0; mt < 2; mt++)
#pragma unroll
                for (int nt = 0; nt < 8; nt++)
                    mma_tf32(acc[mt][nt], a[mt], b[nt]);
        }
    }

    const int cm = blockIdx.y * 128 + wm * 32;
    const int cn = blockIdx.x * 128 + wn * 64;
#pragma unroll
    for (int mt = 0; mt < 2; mt++) {
#pragma unroll
        for (int nt = 0; nt < 8; nt++) {
            float* p0 = C + (size_t)(cm + mt * 16 + gid) * N + cn + nt * 8 + 2 * tig;
            float* p1 = p0 + (size_t)8 * N;
            *(float2*)p0 = make_float2(acc[mt][nt][0], acc[mt][nt][1]);
            *(float2*)p1 = make_float2(acc[mt][nt][2], acc[mt][nt][3]);
        }
    }
}

// ---------------------------------------------------------------------------
// Tensor-core flash attention (tf32), causal, GQA. Inputs pre-rounded.
// ---------------------------------------------------------------------------
#define KPITCH 68
#define VPITCH 72
#define PPITCH 68
#define KBUF (64 * KPITCH)
#define VBUF (64 * VPITCH)
#define SMEM_ATTN ((2 * KBUF + 2 * VBUF + 4 * 16 * PPITCH) * 4)

__global__ __launch_bounds__(128) void attn_tc(
    const float* __restrict__ Q, const float* __restrict__ Kg,
    const float* __restrict__ Vg, float* __restrict__ O)
{
    extern __shared__ char smem_raw[];
    float*    sK = (float*)smem_raw;
    float*    sV = (float*)(smem_raw + 2 * KBUF * 4);
    uint32_t* sP = (uint32_t*)(smem_raw + (2 * KBUF + 2 * VBUF) * 4);

    const int qt = blockIdx.x, h = blockIdx.y, b = blockIdx.z;
    const int kvh = h >> 2;
    const int tid = threadIdx.x;
    const int w = tid >> 5;
    const int lane = tid & 31;
    const int gid = lane >> 2, tig = lane & 3;

    const int qr0 = qt * 64 + w * 16 + gid;
    const int qr1 = qr0 + 8;

    uint32_t aq[8][4];
    {
        const float* q0 = Q + ((size_t)(b * NSEQ) + qr0) * DMODEL + h * HD;
        const float* q1 = Q + ((size_t)(b * NSEQ) + qr1) * DMODEL + h * HD;
#pragma unroll
        for (int ks = 0; ks < 8; ks++) {
            int d = ks * 8 + tig;
            aq[ks][0] = __float_as_uint(q0[d] * 0.125f);
            aq[ks][1] = __float_as_uint(q1[d] * 0.125f);
            aq[ks][2] = __float_as_uint(q0[d + 4] * 0.125f);
            aq[ks][3] = __float_as_uint(q1[d + 4] * 0.125f);
        }
    }

    float o[8][4];
#pragma unroll
    for (int nt = 0; nt < 8; nt++)
#pragma unroll
        for (int i = 0; i < 4; i++) o[nt][i] = 0.f;
    float m0 = -1e30f, l0 = 0.f, m1 = -1e30f, l1 = 0.f;

    const size_t kvs = NKVH * HD;

    auto load_tile = [&](int t, int st) {
        const float* kb = Kg + (size_t)(b * NSEQ + t * 64) * kvs + kvh * HD;
        const float* vb = Vg + (size_t)(b * NSEQ + t * 64) * kvs + kvh * HD;
        float* dK = sK + st * KBUF;
        float* dV = sV + st * VBUF;
#pragma unroll
        for (int i = 0; i < 8; i++) {
            int c = tid + i * 128;
            int r = c >> 4, c4 = (c & 15) << 2;
            cp_async16(dK + r * KPITCH + c4, kb + (size_t)r * kvs + c4);
            cp_async16(dV + r * VPITCH + c4, vb + (size_t)r * kvs + c4);
        }
    };

    load_tile(0, 0);
    CP_COMMIT();

    for (int t = 0; t <= qt; t++) {
        const int st = t & 1;
        CP_WAIT0();
        __syncthreads();

        if (t < qt) { load_tile(t + 1, st ^ 1); CP_COMMIT(); }

        const float* bK = sK + st * KBUF;
        const float* bV = sV + st * VBUF;

        float s[8][4];
#pragma unroll
        for (int nt = 0; nt < 8; nt++)
#pragma unroll
            for (int i = 0; i < 4; i++) s[nt][i] = 0.f;
#pragma unroll
        for (int ks = 0; ks < 8; ks++) {
            const int d0 = ks * 8;
#pragma unroll
            for (int nt = 0; nt < 8; nt++) {
                const float* kr = bK + (nt * 8 + gid) * KPITCH + d0 + tig;
                uint32_t bb[2];
                bb[0] = __float_as_uint(kr[0]);
                bb[1] = __float_as_uint(kr[4]);
                mma_tf32(s[nt], aq[ks], bb);
            }
        }

        if (t == qt) {
#pragma unroll
            for (int nt = 0; nt < 8; nt++) {
                int k0 = nt * 8 + 2 * tig;
                int r0 = w * 16 + gid;
                if (k0 > r0)         s[nt][0] = -1e30f;
                if (k0 + 1 > r0)     s[nt][1] = -1e30f;
                if (k0 > r0 + 8)     s[nt][2] = -1e30f;
                if (k0 + 1 > r0 + 8) s[nt][3] = -1e30f;
            }
        }

        float mx0 = -1e30f, mx1 = -1e30f;
#pragma unroll
        for (int nt = 0; nt < 8; nt++) {
            mx0 = fmaxf(mx0, fmaxf(s[nt][0], s[nt][1]));
            mx1 = fmaxf(mx1, fmaxf(s[nt][2], s[nt][3]));
        }
        mx0 = fmaxf(mx0, __shfl_xor_sync(0xffffffffu, mx0, 1));
        mx0 = fmaxf(mx0, __shfl_xor_sync(0xffffffffu, mx0, 2));
        mx1 = fmaxf(mx1, __shfl_xor_sync(0xffffffffu, mx1, 1));
        mx1 = fmaxf(mx1, __shfl_xor_sync(0xffffffffu, mx1, 2));

        float mn0 = fmaxf(m0, mx0), mn1 = fmaxf(m1, mx1);
        float c0 = __expf(m0 - mn0), c1 = __expf(m1 - mn1);
        float ls0 = 0.f, ls1 = 0.f;
#pragma unroll
        for (int nt = 0; nt < 8; nt++) {
            s[nt][0] = __expf(s[nt][0] - mn0);
            s[nt][1] = __expf(s[nt][1] - mn0);
            s[nt][2] = __expf(s[nt][2] - mn1);
            s[nt][3] = __expf(s[nt][3] - mn1);
            ls0 += s[nt][0] + s[nt][1];
            ls1 += s[nt][2] + s[nt][3];
        }
        ls0 += __shfl_xor_sync(0xffffffffu, ls0, 1);
        ls0 += __shfl_xor_sync(0xffffffffu, ls0, 2);
        ls1 += __shfl_xor_sync(0xffffffffu, ls1, 1);
        ls1 += __shfl_xor_sync(0xffffffffu, ls1, 2);
        l0 = l0 * c0 + ls0;
        l1 = l1 * c1 + ls1;
        m0 = mn0; m1 = mn1;
#pragma unroll
        for (int nt = 0; nt < 8; nt++) {
            o[nt][0] *= c0; o[nt][1] *= c0;
            o[nt][2] *= c1; o[nt][3] *= c1;
        }

        uint32_t* pw = sP + w * (16 * PPITCH);
#pragma unroll
        for (int nt = 0; nt < 8; nt++) {
            uint2 v0 = make_uint2(f2tf32(s[nt][0]), f2tf32(s[nt][1]));
            uint2 v1 = make_uint2(f2tf32(s[nt][2]), f2tf32(s[nt][3]));
            *(uint2*)(pw + gid * PPITCH + nt * 8 + 2 * tig) = v0;
            *(uint2*)(pw + (gid + 8) * PPITCH + nt * 8 + 2 * tig) = v1;
        }
        __syncwarp();

#pragma unroll
        for (int ks = 0; ks < 8; ks++) {
            const int k0 = ks * 8;
            uint32_t ap[4];
            ap[0] = pw[gid * PPITCH + k0 + tig];
            ap[1] = pw[(gid + 8) * PPITCH + k0 + tig];
            ap[2] = pw[gid * PPITCH + k0 + tig + 4];
            ap[3] = pw[(gid + 8) * PPITCH + k0 + tig + 4];
#pragma unroll
            for (int nt = 0; nt < 8; nt++) {
                const float* vr = bV + (k0 + tig) * VPITCH + nt * 8 + gid;
                uint32_t bb[2];
                bb[0] = __float_as_uint(vr[0]);
                bb[1] = __float_as_uint(vr[4 * VPITCH]);
                mma_tf32(o[nt], ap, bb);
            }
        }
    }

    float inv0 = 1.f / l0, inv1 = 1.f / l1;
    float* o0 = O + ((size_t)(b * NSEQ) + qr0) * DMODEL + h * HD;
    float* o1 = O + ((size_t)(b * NSEQ) + qr1) * DMODEL + h * HD;
#pragma unroll
    for (int nt = 0; nt < 8; nt++) {
        *(float2*)(o0 + nt * 8 + 2 * tig) =
            make_float2(roundtf(o[nt][0] * inv0), roundtf(o[nt][1] * inv0));
        *(float2*)(o1 + nt * 8 + 2 * tig) =
            make_float2(roundtf(o[nt][2] * inv1), roundtf(o[nt][3] * inv1));
    }
}

// ---------------------------------------------------------------------------
// Launch. Order: round_x, round_w, qkv_gemm, attn (ncu slot #4), O-gemm.
// ---------------------------------------------------------------------------
extern "C" void kernel_launch(void* const* d_in, const int* in_sizes, int n_in,
                              void* d_out, int out_size)
{
    const float* x  = (const float*)d_in[0];
    const float* Wq = (const float*)d_in[1];
    const float* Wk = (const float*)d_in[2];
    const float* Wv = (const float*)d_in[3];
    const float* Wo = (const float*)d_in[4];
    const float* fc = (const float*)d_in[5];
    const float* fs = (const float*)d_in[6];
    float* out = (float*)d_out;

    float *Qp, *Kp, *Vp, *Op, *xr, *Wqr, *Wkr, *Wvr, *Wor;
    cudaGetSymbolAddress((void**)&Qp,  g_Q);
    cudaGetSymbolAddress((void**)&Kp,  g_K);
    cudaGetSymbolAddress((void**)&Vp,  g_V);
    cudaGetSymbolAddress((void**)&Op,  g_O);
    cudaGetSymbolAddress((void**)&xr,  g_xr);
    cudaGetSymbolAddress((void**)&Wqr, g_Wqr);
    cudaGetSymbolAddress((void**)&Wkr, g_Wkr);
    cudaGetSymbolAddress((void**)&Wvr, g_Wvr);
    cudaGetSymbolAddress((void**)&Wor, g_Wor);

    static bool attr_set = false;
    if (!attr_set) {
        cudaFuncSetAttribute(attn_tc,
            cudaFuncAttributeMaxDynamicSharedMemorySize, SMEM_ATTN);
        attr_set = true;
    }

    // 1,2: tf32 rounding
    round_x<<<(N4_X + 255) / 256, 256>>>((const float4*)x, (float4*)xr);
    round_w<<<(N4_W_ALL + 255) / 256, 256>>>(
        (const float4*)Wq, (const float4*)Wk, (const float4*)Wv, (const float4*)Wo,
        (float4*)Wqr, (float4*)Wkr, (float4*)Wvr, (float4*)Wor);

    // 3: fused Q/K/V projection + RoPE (768 CTAs)
    qkv_gemm<<<dim3(24, ROWS / 128), 256>>>(
        xr, Wqr, Wkr, Wvr, Qp, Kp, Vp, fc, fs);

    // 4: attention  <-- ncu capture slot
    attn_tc<<<dim3(NSEQ / 64, NH, BATCH), 128, SMEM_ATTN>>>(Qp, Kp, Vp, Op);

    // 5: output projection
    tf32gemm<<<dim3(DMODEL / 128, ROWS / 128), 256>>>(
        Op, Wor, out, ROWS, DMODEL, DMODEL);
}

// round 8
// speedup vs baseline: 6.9498x; 1.0048x over previous
#include <cuda_runtime.h>
#include <math.h>
#include <stdint.h>

// Problem constants
#define BATCH 2
#define NSEQ  2048
#define DMODEL 2048
#define NH    32
#define NKVH  8
#define HD    64
#define ROWS  4096       // BATCH * NSEQ
#define NQT   (NSEQ / 64)   // 32 q-tiles

// ---------------------------------------------------------------------------
// Scratch (device globals -- no allocation allowed anywhere)
// ---------------------------------------------------------------------------
__device__ float g_Q[(size_t)ROWS * DMODEL];
__device__ float g_K[(size_t)ROWS * (NKVH * HD)];
__device__ float g_V[(size_t)ROWS * (NKVH * HD)];
__device__ float g_O[(size_t)ROWS * DMODEL];
__device__ float g_xr[(size_t)ROWS * DMODEL];
__device__ float g_Wqr[(size_t)DMODEL * DMODEL];
__device__ float g_Wkr[(size_t)DMODEL * (NKVH * HD)];
__device__ float g_Wvr[(size_t)DMODEL * (NKVH * HD)];
__device__ float g_Wor[(size_t)DMODEL * DMODEL];

// ---------------------------------------------------------------------------
// Helpers
// ---------------------------------------------------------------------------
__device__ __forceinline__ void cp_async16(void* smem, const void* gmem) {
    uint32_t s = (uint32_t)__cvta_generic_to_shared(smem);
    asm volatile("cp.async.cg.shared.global [%0], [%1], 16;\n" ::"r"(s), "l"(gmem));
}
#define CP_COMMIT() asm volatile("cp.async.commit_group;\n" ::: "memory")
#define CP_WAIT0()  asm volatile("cp.async.wait_group 0;\n" ::: "memory")
#define CP_WAIT1()  asm volatile("cp.async.wait_group 1;\n" ::: "memory")

__device__ __forceinline__ uint32_t f2tf32(float x) {
    uint32_t r;
    asm("cvt.rna.tf32.f32 %0, %1;" : "=r"(r) : "f"(x));
    return r;
}
__device__ __forceinline__ float roundtf(float x) {
    return __uint_as_float(f2tf32(x));
}

__device__ __forceinline__ void mma_tf32(float* c, const uint32_t* a, const uint32_t* b) {
    asm volatile(
        "mma.sync.aligned.m16n8k8.row.col.f32.tf32.tf32.f32 "
        "{%0,%1,%2,%3}, {%4,%5,%6,%7}, {%8,%9}, {%0,%1,%2,%3};"
        : "+f"(c[0]), "+f"(c[1]), "+f"(c[2]), "+f"(c[3])
        : "r"(a[0]), "r"(a[1]), "r"(a[2]), "r"(a[3]), "r"(b[0]), "r"(b[1]));
}

// ---------------------------------------------------------------------------
// Fused tf32 rounding of x and all weights (one launch).
// ---------------------------------------------------------------------------
#define N4_X   ((ROWS * DMODEL) / 4)
#define N4_WQ  ((DMODEL * DMODEL) / 4)
#define N4_WKV ((DMODEL * NKVH * HD) / 4)
#define N4_ALL (N4_X + N4_WQ + 2 * N4_WKV + N4_WQ)

__global__ void round_all(const float4* __restrict__ x,
                          const float4* __restrict__ Wq,
                          const float4* __restrict__ Wk,
                          const float4* __restrict__ Wv,
                          const float4* __restrict__ Wo,
                          float4* __restrict__ xr,
                          float4* __restrict__ Wqr,
                          float4* __restrict__ Wkr,
                          float4* __restrict__ Wvr,
                          float4* __restrict__ Wor)
{
    int i = blockIdx.x * blockDim.x + threadIdx.x;
    if (i >= N4_ALL) return;
    const float4* src;
    float4* dst;
    int j = i;
    if (j < N4_X) { src = x; dst = xr; }
    else {
        j -= N4_X;
        if (j < N4_WQ) { src = Wq; dst = Wqr; }
        else {
            j -= N4_WQ;
            if (j < N4_WKV) { src = Wk; dst = Wkr; }
            else {
                j -= N4_WKV;
                if (j < N4_WKV) { src = Wv; dst = Wvr; }
                else { j -= N4_WKV; src = Wo; dst = Wor; }
            }
        }
    }
    float4 v = src[j];
    dst[j] = make_float4(roundtf(v.x), roundtf(v.y), roundtf(v.z), roundtf(v.w));
}

// ---------------------------------------------------------------------------
// GEMM tiling constants. 3-stage cp.async pipeline, dynamic smem.
// ---------------------------------------------------------------------------
#define APAD 20
#define BPAD 136
#define A_ST (128 * APAD)               // floats per A stage
#define GST  (A_ST + 16 * BPAD)         // floats per stage (4736)
#define GEMM_DYN (3 * GST * 4)          // 56832 bytes

// Fused QKV projection + RoPE epilogue.
// grid (24, 32): bx<16 -> Q tile; [16,20) -> K; [20,24) -> V.
__global__ __launch_bounds__(256, 2) void qkv_gemm(
    const float* __restrict__ A,
    const float* __restrict__ Wq, const float* __restrict__ Wk,
    const float* __restrict__ Wv,
    float* __restrict__ Qo, float* __restrict__ Ko, float* __restrict__ Vo,
    const float* __restrict__ fc, const float* __restrict__ fs)
{
    extern __shared__ float smf[];

    const int tid  = threadIdx.x;
    const int lane = tid & 31;
    const int wid  = tid >> 5;
    const int wm   = wid & 3;
    const int wn   = wid >> 2;
    const int gid  = lane >> 2;
    const int tig  = lane & 3;
    const int bx   = blockIdx.x;

    const float* B;
    float* C;
    int nTile, Ntot, doRope;
    if (bx < 16)      { B = Wq; C = Qo; nTile = bx;      Ntot = DMODEL;    doRope = 1; }
    else if (bx < 20) { B = Wk; C = Ko; nTile = bx - 16; Ntot = NKVH * HD; doRope = 1; }
    else              { B = Wv; C = Vo; nTile = bx - 20; Ntot = NKVH * HD; doRope = 0; }

    const int K = DMODEL;
    const float* Ab = A + (size_t)(blockIdx.y * 128) * K;
    const float* Bb = B + nTile * 128;

    const int am  = tid >> 2;
    const int akq = (tid & 3) << 2;
    const int bk  = tid >> 5;
    const int bnq = (tid & 31) << 2;

    auto load_stage = [&](int kt, int s) {
        float* Ad = smf + s * GST;
        float* Bd = smf + s * GST + A_ST;
        const int k0 = kt * 16;
        cp_async16(Ad + am * APAD + akq,        Ab + (size_t)am * K + k0 + akq);
        cp_async16(Ad + (am + 64) * APAD + akq, Ab + (size_t)(am + 64) * K + k0 + akq);
        cp_async16(Bd + bk * BPAD + bnq,        Bb + (size_t)(k0 + bk) * Ntot + bnq);
        cp_async16(Bd + (bk + 8) * BPAD + bnq,  Bb + (size_t)(k0 + bk + 8) * Ntot + bnq);
    };

    float acc[2][8][4];
#pragma unroll
    for (int mt = 0; mt < 2; mt++)
#pragma unroll
        for (int nt = 0; nt < 8; nt++)
#pragma unroll
            for (int i = 0; i < 4; i++) acc[mt][nt][i] = 0.f;

    const int nk = K / 16;
    load_stage(0, 0); CP_COMMIT();
    load_stage(1, 1); CP_COMMIT();

    int st = 0;
    for (int kt = 0; kt < nk; kt++) {
        if (kt < nk - 1) { CP_WAIT1(); } else { CP_WAIT0(); }
        __syncthreads();

        if (kt + 2 < nk) {
            int s2 = st + 2; if (s2 >= 3) s2 -= 3;
            load_stage(kt + 2, s2);
            CP_COMMIT();
        }

        const float* Asb = smf + st * GST;
        const float* Bsb = smf + st * GST + A_ST;
#pragma unroll
        for (int ks = 0; ks < 2; ks++) {
            const int k0 = ks * 8;
            uint32_t a[2][4];
#pragma unroll
            for (int mt = 0; mt < 2; mt++) {
                const int mr = wm * 32 + mt * 16;
                a[mt][0] = __float_as_uint(Asb[(mr + gid) * APAD + k0 + tig]);
                a[mt][1] = __float_as_uint(Asb[(mr + gid + 8) * APAD + k0 + tig]);
                a[mt][2] = __float_as_uint(Asb[(mr + gid) * APAD + k0 + tig + 4]);
                a[mt][3] = __float_as_uint(Asb[(mr + gid + 8) * APAD + k0 + tig + 4]);
            }
            uint32_t b[8][2];
#pragma unroll
            for (int nt = 0; nt < 8; nt++) {
                const int nc = wn * 64 + nt * 8 + gid;
                b[nt][0] = __float_as_uint(Bsb[(k0 + tig) * BPAD + nc]);
                b[nt][1] = __float_as_uint(Bsb[(k0 + tig + 4) * BPAD + nc]);
            }
#pragma unroll
            for (int mt = 0; mt < 2; mt++)
#pragma unroll
                for (int nt = 0; nt < 8; nt++)
                    mma_tf32(acc[mt][nt], a[mt], b[nt]);
        }
        st++; if (st == 3) st = 0;
    }

    // Epilogue with fused RoPE (pairs are (even,odd) columns = acc[..][0/1]).
    const int cm = blockIdx.y * 128 + wm * 32;
    const int cn = nTile * 128 + wn * 64;
#pragma unroll
    for (int mt = 0; mt < 2; mt++) {
        const int r0 = cm + mt * 16 + gid;
        const int r1 = r0 + 8;
#pragma unroll
        for (int nt = 0; nt < 8; nt++) {
            const int col = cn + nt * 8 + 2 * tig;
            float* p0 = C + (size_t)r0 * Ntot + col;
            float* p1 = C + (size_t)r1 * Ntot + col;
            if (doRope) {
                const int p  = (col >> 1) & 31;
                const int n0 = r0 & (NSEQ - 1);
                const int n1 = r1 & (NSEQ - 1);
                float c0 = fc[n0 * 32 + p], s0 = fs[n0 * 32 + p];
                float c1 = fc[n1 * 32 + p], s1 = fs[n1 * 32 + p];
                float xr0 = acc[mt][nt][0], xi0 = acc[mt][nt][1];
                float xr1 = acc[mt][nt][2], xi1 = acc[mt][nt][3];
                *(float2*)p0 = make_float2(roundtf(xr0 * c0 - xi0 * s0),
                                           roundtf(xr0 * s0 + xi0 * c0));
                *(float2*)p1 = make_float2(roundtf(xr1 * c1 - xi1 * s1),
                                           roundtf(xr1 * s1 + xi1 * c1));
            } else {
                *(float2*)p0 = make_float2(roundtf(acc[mt][nt][0]),
                                           roundtf(acc[mt][nt][1]));
                *(float2*)p1 = make_float2(roundtf(acc[mt][nt][2]),
                                           roundtf(acc[mt][nt][3]));
            }
        }
    }
}

// Plain GEMM for the output projection (3-stage pipeline).
__global__ __launch_bounds__(256, 2) void tf32gemm(
    const float* __restrict__ A, const float* __restrict__ B,
    float* __restrict__ C, int M, int N, int K)
{
    extern __shared__ float smf[];

    const int tid  = threadIdx.x;
    const int lane = tid & 31;
    const int wid  = tid >> 5;
    const int wm   = wid & 3;
    const int wn   = wid >> 2;
    const int gid  = lane >> 2;
    const int tig  = lane & 3;

    const float* Ab = A + (size_t)(blockIdx.y * 128) * K;
    const float* Bb = B + blockIdx.x * 128;

    const int am  = tid >> 2;
    const int akq = (tid & 3) << 2;
    const int bk  = tid >> 5;
    const int bnq = (tid & 31) << 2;

    auto load_stage = [&](int kt, int s) {
        float* Ad = smf + s * GST;
        float* Bd = smf + s * GST + A_ST;
        const int k0 = kt * 16;
        cp_async16(Ad + am * APAD + akq,        Ab + (size_t)am * K + k0 + akq);
        cp_async16(Ad + (am + 64) * APAD + akq, Ab + (size_t)(am + 64) * K + k0 + akq);
        cp_async16(Bd + bk * BPAD + bnq,        Bb + (size_t)(k0 + bk) * N + bnq);
        cp_async16(Bd + (bk + 8) * BPAD + bnq,  Bb + (size_t)(k0 + bk + 8) * N + bnq);
    };

    float acc[2][8][4];
#pragma unroll
    for (int mt = 0; mt < 2; mt++)
#pragma unroll
        for (int nt = 0; nt < 8; nt++)
#pragma unroll
            for (int i = 0; i < 4; i++) acc[mt][nt][i] = 0.f;

    const int nk = K / 16;
    load_stage(0, 0); CP_COMMIT();
    load_stage(1, 1); CP_COMMIT();

    int st = 0;
    for (int kt = 0; kt < nk; kt++) {
        if (kt < nk - 1) { CP_WAIT1(); } else { CP_WAIT0(); }
        __syncthreads();

        if (kt + 2 < nk) {
            int s2 = st + 2; if (s2 >= 3) s2 -= 3;
            load_stage(kt + 2, s2);
            CP_COMMIT();
        }

        const float* Asb = smf + st * GST;
        const float* Bsb = smf + st * GST + A_ST;
#pragma unroll
        for (int ks = 0; ks < 2; ks++) {
            const int k0 = ks * 8;
            uint32_t a[2][4];
#pragma unroll
            for (int mt = 0; mt < 2; mt++) {
                const int mr = wm * 32 + mt * 16;
                a[mt][0] = __float_as_uint(Asb[(mr + gid) * APAD + k0 + tig]);
                a[mt][1] = __float_as_uint(Asb[(mr + gid + 8) * APAD + k0 + tig]);
                a[mt][2] = __float_as_uint(Asb[(mr + gid) * APAD + k0 + tig + 4]);
                a[mt][3] = __float_as_uint(Asb[(mr + gid + 8) * APAD + k0 + tig + 4]);
            }
            uint32_t b[8][2];
#pragma unroll
            for (int nt = 0; nt < 8; nt++) {
                const int nc = wn * 64 + nt * 8 + gid;
                b[nt][0] = __float_as_uint(Bsb[(k0 + tig) * BPAD + nc]);
                b[nt][1] = __float_as_uint(Bsb[(k0 + tig + 4) * BPAD + nc]);
            }
#pragma unroll
            for (int mt = 0; mt < 2; mt++)
#pragma unroll
                for (int nt = 0; nt < 8; nt++)
                    mma_tf32(acc[mt][nt], a[mt], b[nt]);
        }
        st++; if (st == 3) st = 0;
    }

    const int cm = blockIdx.y * 128 + wm * 32;
    const int cn = blockIdx.x * 128 + wn * 64;
#pragma unroll
    for (int mt = 0; mt < 2; mt++) {
#pragma unroll
        for (int nt = 0; nt < 8; nt++) {
            float* p0 = C + (size_t)(cm + mt * 16 + gid) * N + cn + nt * 8 + 2 * tig;
            float* p1 = p0 + (size_t)8 * N;
            *(float2*)p0 = make_float2(acc[mt][nt][0], acc[mt][nt][1]);
            *(float2*)p1 = make_float2(acc[mt][nt][2], acc[mt][nt][3]);
        }
    }
}

// ---------------------------------------------------------------------------
// Tensor-core flash attention (tf32), causal, GQA.
// LPT schedule: qt = NQT-1 - blockIdx.x so heaviest CTAs launch first.
// ---------------------------------------------------------------------------
#define KPITCH 68
#define VPITCH 72
#define PPITCH 68
#define KBUF (64 * KPITCH)
#define VBUF (64 * VPITCH)
#define SMEM_ATTN ((2 * KBUF + 2 * VBUF + 4 * 16 * PPITCH) * 4)

__global__ __launch_bounds__(128) void attn_tc(
    const float* __restrict__ Q, const float* __restrict__ Kg,
    const float* __restrict__ Vg, float* __restrict__ O)
{
    extern __shared__ char smem_raw[];
    float*    sK = (float*)smem_raw;
    float*    sV = (float*)(smem_raw + 2 * KBUF * 4);
    uint32_t* sP = (uint32_t*)(smem_raw + (2 * KBUF + 2 * VBUF) * 4);

    const int qt = NQT - 1 - blockIdx.x;   // LPT: big tiles first
    const int h = blockIdx.y, b = blockIdx.z;
    const int kvh = h >> 2;
    const int tid = threadIdx.x;
    const int w = tid >> 5;
    const int lane = tid & 31;
    const int gid = lane >> 2, tig = lane & 3;

    const int qr0 = qt * 64 + w * 16 + gid;
    const int qr1 = qr0 + 8;

    uint32_t aq[8][4];
    {
        const float* q0 = Q + ((size_t)(b * NSEQ) + qr0) * DMODEL + h * HD;
        const float* q1 = Q + ((size_t)(b * NSEQ) + qr1) * DMODEL + h * HD;
#pragma unroll
        for (int ks = 0; ks < 8; ks++) {
            int d = ks * 8 + tig;
            aq[ks][0] = __float_as_uint(q0[d] * 0.125f);
            aq[ks][1] = __float_as_uint(q1[d] * 0.125f);
            aq[ks][2] = __float_as_uint(q0[d + 4] * 0.125f);
            aq[ks][3] = __float_as_uint(q1[d + 4] * 0.125f);
        }
    }

    float o[8][4];
#pragma unroll
    for (int nt = 0; nt < 8; nt++)
#pragma unroll
        for (int i = 0; i < 4; i++) o[nt][i] = 0.f;
    float m0 = -1e30f, l0 = 0.f, m1 = -1e30f, l1 = 0.f;

    const size_t kvs = NKVH * HD;

    auto load_tile = [&](int t, int st) {
        const float* kb = Kg + (size_t)(b * NSEQ + t * 64) * kvs + kvh * HD;
        const float* vb = Vg + (size_t)(b * NSEQ + t * 64) * kvs + kvh * HD;
        float* dK = sK + st * KBUF;
        float* dV = sV + st * VBUF;
#pragma unroll
        for (int i = 0; i < 8; i++) {
            int c = tid + i * 128;
            int r = c >> 4, c4 = (c & 15) << 2;
            cp_async16(dK + r * KPITCH + c4, kb + (size_t)r * kvs + c4);
            cp_async16(dV + r * VPITCH + c4, vb + (size_t)r * kvs + c4);
        }
    };

    load_tile(0, 0);
    CP_COMMIT();

    for (int t = 0; t <= qt; t++) {
        const int st = t & 1;
        CP_WAIT0();
        __syncthreads();

        if (t < qt) { load_tile(t + 1, st ^ 1); CP_COMMIT(); }

        const float* bK = sK + st * KBUF;
        const float* bV = sV + st * VBUF;

        float s[8][4];
#pragma unroll
        for (int nt = 0; nt < 8; nt++)
#pragma unroll
            for (int i = 0; i < 4; i++) s[nt][i] = 0.f;
#pragma unroll
        for (int ks = 0; ks < 8; ks++) {
            const int d0 = ks * 8;
#pragma unroll
            for (int nt = 0; nt < 8; nt++) {
                const float* kr = bK + (nt * 8 + gid) * KPITCH + d0 + tig;
                uint32_t bb[2];
                bb[0] = __float_as_uint(kr[0]);
                bb[1] = __float_as_uint(kr[4]);
                mma_tf32(s[nt], aq[ks], bb);
            }
        }

        if (t == qt) {
#pragma unroll
            for (int nt = 0; nt < 8; nt++) {
                int k0 = nt * 8 + 2 * tig;
                int r0 = w * 16 + gid;
                if (k0 > r0)         s[nt][0] = -1e30f;
                if (k0 + 1 > r0)     s[nt][1] = -1e30f;
                if (k0 > r0 + 8)     s[nt][2] = -1e30f;
                if (k0 + 1 > r0 + 8) s[nt][3] = -1e30f;
            }
        }

        float mx0 = -1e30f, mx1 = -1e30f;
#pragma unroll
        for (int nt = 0; nt < 8; nt++) {
            mx0 = fmaxf(mx0, fmaxf(s[nt][0], s[nt][1]));
            mx1 = fmaxf(mx1, fmaxf(s[nt][2], s[nt][3]));
        }
        mx0 = fmaxf(mx0, __shfl_xor_sync(0xffffffffu, mx0, 1));
        mx0 = fmaxf(mx0, __shfl_xor_sync(0xffffffffu, mx0, 2));
        mx1 = fmaxf(mx1, __shfl_xor_sync(0xffffffffu, mx1, 1));
        mx1 = fmaxf(mx1, __shfl_xor_sync(0xffffffffu, mx1, 2));

        float mn0 = fmaxf(m0, mx0), mn1 = fmaxf(m1, mx1);
        float c0 = __expf(m0 - mn0), c1 = __expf(m1 - mn1);
        float ls0 = 0.f, ls1 = 0.f;
#pragma unroll
        for (int nt = 0; nt < 8; nt++) {
            s[nt][0] = __expf(s[nt][0] - mn0);
            s[nt][1] = __expf(s[nt][1] - mn0);
            s[nt][2] = __expf(s[nt][2] - mn1);
            s[nt][3] = __expf(s[nt][3] - mn1);
            ls0 += s[nt][0] + s[nt][1];
            ls1 += s[nt][2] + s[nt][3];
        }
        ls0 += __shfl_xor_sync(0xffffffffu, ls0, 1);
        ls0 += __shfl_xor_sync(0xffffffffu, ls0, 2);
        ls1 += __shfl_xor_sync(0xffffffffu, ls1, 1);
        ls1 += __shfl_xor_sync(0xffffffffu, ls1, 2);
        l0 = l0 * c0 + ls0;
        l1 = l1 * c1 + ls1;
        m0 = mn0; m1 = mn1;
#pragma unroll
        for (int nt = 0; nt < 8; nt++) {
            o[nt][0] *= c0; o[nt][1] *= c0;
            o[nt][2] *= c1; o[nt][3] *= c1;
        }

        uint32_t* pw = sP + w * (16 * PPITCH);
#pragma unroll
        for (int nt = 0; nt < 8; nt++) {
            uint2 v0 = make_uint2(f2tf32(s[nt][0]), f2tf32(s[nt][1]));
            uint2 v1 = make_uint2(f2tf32(s[nt][2]), f2tf32(s[nt][3]));
            *(uint2*)(pw + gid * PPITCH + nt * 8 + 2 * tig) = v0;
            *(uint2*)(pw + (gid + 8) * PPITCH + nt * 8 + 2 * tig) = v1;
        }
        __syncwarp();

#pragma unroll
        for (int ks = 0; ks < 8; ks++) {
            const int k0 = ks * 8;
            uint32_t ap[4];
            ap[0] = pw[gid * PPITCH + k0 + tig];
            ap[1] = pw[(gid + 8) * PPITCH + k0 + tig];
            ap[2] = pw[gid * PPITCH + k0 + tig + 4];
            ap[3] = pw[(gid + 8) * PPITCH + k0 + tig + 4];
#pragma unroll
            for (int nt = 0; nt < 8; nt++) {
                const float* vr = bV + (k0 + tig) * VPITCH + nt * 8 + gid;
                uint32_t bb[2];
                bb[0] = __float_as_uint(vr[0]);
                bb[1] = __float_as_uint(vr[4 * VPITCH]);
                mma_tf32(o[nt], ap, bb);
            }
        }
    }

    float inv0 = 1.f / l0, inv1 = 1.f / l1;
    float* o0 = O + ((size_t)(b * NSEQ) + qr0) * DMODEL + h * HD;
    float* o1 = O + ((size_t)(b * NSEQ) + qr1) * DMODEL + h * HD;
#pragma unroll
    for (int nt = 0; nt < 8; nt++) {
        *(float2*)(o0 + nt * 8 + 2 * tig) =
            make_float2(roundtf(o[nt][0] * inv0), roundtf(o[nt][1] * inv0));
        *(float2*)(o1 + nt * 8 + 2 * tig) =
            make_float2(roundtf(o[nt][2] * inv1), roundtf(o[nt][3] * inv1));
    }
}

// ---------------------------------------------------------------------------
// Launch. Order: round_all(1), qkv(2), attn(3), O-gemm(4 = ncu slot).
// ---------------------------------------------------------------------------
extern "C" void kernel_launch(void* const* d_in, const int* in_sizes, int n_in,
                              void* d_out, int out_size)
{
    const float* x  = (const float*)d_in[0];
    const float* Wq = (const float*)d_in[1];
    const float* Wk = (const float*)d_in[2];
    const float* Wv = (const float*)d_in[3];
    const float* Wo = (const float*)d_in[4];
    const float* fc = (const float*)d_in[5];
    const float* fs = (const float*)d_in[6];
    float* out = (float*)d_out;

    float *Qp, *Kp, *Vp, *Op, *xr, *Wqr, *Wkr, *Wvr, *Wor;
    cudaGetSymbolAddress((void**)&Qp,  g_Q);
    cudaGetSymbolAddress((void**)&Kp,  g_K);
    cudaGetSymbolAddress((void**)&Vp,  g_V);
    cudaGetSymbolAddress((void**)&Op,  g_O);
    cudaGetSymbolAddress((void**)&xr,  g_xr);
    cudaGetSymbolAddress((void**)&Wqr, g_Wqr);
    cudaGetSymbolAddress((void**)&Wkr, g_Wkr);
    cudaGetSymbolAddress((void**)&Wvr, g_Wvr);
    cudaGetSymbolAddress((void**)&Wor, g_Wor);

    static bool attr_set = false;
    if (!attr_set) {
        cudaFuncSetAttribute(attn_tc,
            cudaFuncAttributeMaxDynamicSharedMemorySize, SMEM_ATTN);
        cudaFuncSetAttribute(qkv_gemm,
            cudaFuncAttributeMaxDynamicSharedMemorySize, GEMM_DYN);
        cudaFuncSetAttribute(tf32gemm,
            cudaFuncAttributeMaxDynamicSharedMemorySize, GEMM_DYN);
        attr_set = true;
    }

    // 1: fused tf32 rounding
    round_all<<<(N4_ALL + 255) / 256, 256>>>(
        (const float4*)x, (const float4*)Wq, (const float4*)Wk,
        (const float4*)Wv, (const float4*)Wo,
        (float4*)xr, (float4*)Wqr, (float4*)Wkr, (float4*)Wvr, (float4*)Wor);

    // 2: fused Q/K/V projection + RoPE
    qkv_gemm<<<dim3(24, ROWS / 128), 256, GEMM_DYN>>>(
        xr, Wqr, Wkr, Wvr, Qp, Kp, Vp, fc, fs);

    // 3: attention (LPT-ordered)
    attn_tc<<<dim3(NQT, NH, BATCH), 128, SMEM_ATTN>>>(Qp, Kp, Vp, Op);

    // 4: output projection  <-- ncu capture slot
    tf32gemm<<<dim3(DMODEL / 128, ROWS / 128), 256, GEMM_DYN>>>(
        Op, Wor, out, ROWS, DMODEL, DMODEL);
}

// round 9
// speedup vs baseline: 7.2051x; 1.0367x over previous
#include <cuda_runtime.h>
#include <math.h>
#include <stdint.h>

// Problem constants
#define BATCH 2
#define NSEQ  2048
#define DMODEL 2048
#define NH    32
#define NKVH  8
#define HD    64
#define ROWS  4096       // BATCH * NSEQ
#define NQT   (NSEQ / 64)   // 32 q-tiles

// ---------------------------------------------------------------------------
// Scratch (device globals -- no allocation allowed anywhere)
// ---------------------------------------------------------------------------
__device__ float g_Q[(size_t)ROWS * DMODEL];
__device__ float g_K[(size_t)ROWS * (NKVH * HD)];
__device__ float g_V[(size_t)ROWS * (NKVH * HD)];
__device__ float g_O[(size_t)ROWS * DMODEL];
__device__ float g_xr[(size_t)ROWS * DMODEL];
__device__ float g_Wqr[(size_t)DMODEL * DMODEL];
__device__ float g_Wkr[(size_t)DMODEL * (NKVH * HD)];
__device__ float g_Wvr[(size_t)DMODEL * (NKVH * HD)];
__device__ float g_Wor[(size_t)DMODEL * DMODEL];

// ---------------------------------------------------------------------------
// Helpers
// ---------------------------------------------------------------------------
__device__ __forceinline__ void cp_async16(void* smem, const void* gmem) {
    uint32_t s = (uint32_t)__cvta_generic_to_shared(smem);
    asm volatile("cp.async.cg.shared.global [%0], [%1], 16;\n" ::"r"(s), "l"(gmem));
}
#define CP_COMMIT() asm volatile("cp.async.commit_group;\n" ::: "memory")
#define CP_WAIT0()  asm volatile("cp.async.wait_group 0;\n" ::: "memory")
#define CP_WAIT1()  asm volatile("cp.async.wait_group 1;\n" ::: "memory")

__device__ __forceinline__ uint32_t f2tf32(float x) {
    uint32_t r;
    asm("cvt.rna.tf32.f32 %0, %1;" : "=r"(r) : "f"(x));
    return r;
}
__device__ __forceinline__ float roundtf(float x) {
    return __uint_as_float(f2tf32(x));
}

__device__ __forceinline__ void mma_tf32(float* c, const uint32_t* a, const uint32_t* b) {
    asm volatile(
        "mma.sync.aligned.m16n8k8.row.col.f32.tf32.tf32.f32 "
        "{%0,%1,%2,%3}, {%4,%5,%6,%7}, {%8,%9}, {%0,%1,%2,%3};"
        : "+f"(c[0]), "+f"(c[1]), "+f"(c[2]), "+f"(c[3])
        : "r"(a[0]), "r"(a[1]), "r"(a[2]), "r"(a[3]), "r"(b[0]), "r"(b[1]));
}

// ---------------------------------------------------------------------------
// Fused tf32 rounding of x and all weights (one launch).
// ---------------------------------------------------------------------------
#define N4_X   ((ROWS * DMODEL) / 4)
#define N4_WQ  ((DMODEL * DMODEL) / 4)
#define N4_WKV ((DMODEL * NKVH * HD) / 4)
#define N4_ALL (N4_X + N4_WQ + 2 * N4_WKV + N4_WQ)

__global__ void round_all(const float4* __restrict__ x,
                          const float4* __restrict__ Wq,
                          const float4* __restrict__ Wk,
                          const float4* __restrict__ Wv,
                          const float4* __restrict__ Wo,
                          float4* __restrict__ xr,
                          float4* __restrict__ Wqr,
                          float4* __restrict__ Wkr,
                          float4* __restrict__ Wvr,
                          float4* __restrict__ Wor)
{
    int i = blockIdx.x * blockDim.x + threadIdx.x;
    if (i >= N4_ALL) return;
    const float4* src;
    float4* dst;
    int j = i;
    if (j < N4_X) { src = x; dst = xr; }
    else {
        j -= N4_X;
        if (j < N4_WQ) { src = Wq; dst = Wqr; }
        else {
            j -= N4_WQ;
            if (j < N4_WKV) { src = Wk; dst = Wkr; }
            else {
                j -= N4_WKV;
                if (j < N4_WKV) { src = Wv; dst = Wvr; }
                else { j -= N4_WKV; src = Wo; dst = Wor; }
            }
        }
    }
    float4 v = src[j];
    dst[j] = make_float4(roundtf(v.x), roundtf(v.y), roundtf(v.z), roundtf(v.w));
}

// ---------------------------------------------------------------------------
// GEMM tiling: block 128x128, BK=32 per stage, 3-stage cp.async pipeline.
// A stage: 128 rows x 32 k (pitch 36); B stage: 32 k x 128 n (pitch 136).
// ---------------------------------------------------------------------------
#define APAD 36
#define BPAD 136
#define A_ST (128 * APAD)                 // 4608 floats
#define B_ST (32 * BPAD)                  // 4352 floats
#define GST  (A_ST + B_ST)                // 8960 floats per stage
#define GEMM_DYN (3 * GST * 4)            // 107520 bytes

// Fused QKV projection + RoPE epilogue.
// grid (24, 32): bx<16 -> Q tile; [16,20) -> K; [20,24) -> V.
__global__ __launch_bounds__(256, 2) void qkv_gemm(
    const float* __restrict__ A,
    const float* __restrict__ Wq, const float* __restrict__ Wk,
    const float* __restrict__ Wv,
    float* __restrict__ Qo, float* __restrict__ Ko, float* __restrict__ Vo,
    const float* __restrict__ fc, const float* __restrict__ fs)
{
    extern __shared__ float smf[];

    const int tid  = threadIdx.x;
    const int lane = tid & 31;
    const int wid  = tid >> 5;
    const int wm   = wid & 3;
    const int wn   = wid >> 2;
    const int gid  = lane >> 2;
    const int tig  = lane & 3;
    const int bx   = blockIdx.x;

    const float* B;
    float* C;
    int nTile, Ntot, doRope;
    if (bx < 16)      { B = Wq; C = Qo; nTile = bx;      Ntot = DMODEL;    doRope = 1; }
    else if (bx < 20) { B = Wk; C = Ko; nTile = bx - 16; Ntot = NKVH * HD; doRope = 1; }
    else              { B = Wv; C = Vo; nTile = bx - 20; Ntot = NKVH * HD; doRope = 0; }

    const int K = DMODEL;
    const float* Ab = A + (size_t)(blockIdx.y * 128) * K;
    const float* Bb = B + nTile * 128;

    // A stage: 1024 float4 chunks; c = tid + i*256; row=c>>3, kq=(c&7)*4
    // B stage: 1024 float4 chunks; row=c>>5, nq=(c&31)*4
    auto load_stage = [&](int kt, int s) {
        float* Ad = smf + s * GST;
        float* Bd = smf + s * GST + A_ST;
        const int k0 = kt * 32;
#pragma unroll
        for (int i = 0; i < 4; i++) {
            int c = tid + i * 256;
            int ar = c >> 3, akq = (c & 7) << 2;
            cp_async16(Ad + ar * APAD + akq, Ab + (size_t)ar * K + k0 + akq);
            int br = c >> 5, bnq = (c & 31) << 2;
            cp_async16(Bd + br * BPAD + bnq, Bb + (size_t)(k0 + br) * Ntot + bnq);
        }
    };

    float acc[2][8][4];
#pragma unroll
    for (int mt = 0; mt < 2; mt++)
#pragma unroll
        for (int nt = 0; nt < 8; nt++)
#pragma unroll
            for (int i = 0; i < 4; i++) acc[mt][nt][i] = 0.f;

    const int nk = K / 32;   // 64
    load_stage(0, 0); CP_COMMIT();
    load_stage(1, 1); CP_COMMIT();

    int st = 0;
    for (int kt = 0; kt < nk; kt++) {
        if (kt < nk - 1) { CP_WAIT1(); } else { CP_WAIT0(); }
        __syncthreads();

        if (kt + 2 < nk) {
            int s2 = st + 2; if (s2 >= 3) s2 -= 3;
            load_stage(kt + 2, s2);
            CP_COMMIT();
        }

        const float* Asb = smf + st * GST;
        const float* Bsb = smf + st * GST + A_ST;
#pragma unroll
        for (int ks = 0; ks < 4; ks++) {
            const int k0 = ks * 8;
            uint32_t a[2][4];
#pragma unroll
            for (int mt = 0; mt < 2; mt++) {
                const int mr = wm * 32 + mt * 16;
                a[mt][0] = __float_as_uint(Asb[(mr + gid) * APAD + k0 + tig]);
                a[mt][1] = __float_as_uint(Asb[(mr + gid + 8) * APAD + k0 + tig]);
                a[mt][2] = __float_as_uint(Asb[(mr + gid) * APAD + k0 + tig + 4]);
                a[mt][3] = __float_as_uint(Asb[(mr + gid + 8) * APAD + k0 + tig + 4]);
            }
            uint32_t b[8][2];
#pragma unroll
            for (int nt = 0; nt < 8; nt++) {
                const int nc = wn * 64 + nt * 8 + gid;
                b[nt][0] = __float_as_uint(Bsb[(k0 + tig) * BPAD + nc]);
                b[nt][1] = __float_as_uint(Bsb[(k0 + tig + 4) * BPAD + nc]);
            }
#pragma unroll
            for (int mt = 0; mt < 2; mt++)
#pragma unroll
                for (int nt = 0; nt < 8; nt++)
                    mma_tf32(acc[mt][nt], a[mt], b[nt]);
        }
        st++; if (st == 3) st = 0;
    }

    // Epilogue with fused RoPE (pairs are (even,odd) columns = acc[..][0/1]).
    const int cm = blockIdx.y * 128 + wm * 32;
    const int cn = nTile * 128 + wn * 64;
#pragma unroll
    for (int mt = 0; mt < 2; mt++) {
        const int r0 = cm + mt * 16 + gid;
        const int r1 = r0 + 8;
#pragma unroll
        for (int nt = 0; nt < 8; nt++) {
            const int col = cn + nt * 8 + 2 * tig;
            float* p0 = C + (size_t)r0 * Ntot + col;
            float* p1 = C + (size_t)r1 * Ntot + col;
            if (doRope) {
                const int p  = (col >> 1) & 31;
                const int n0 = r0 & (NSEQ - 1);
                const int n1 = r1 & (NSEQ - 1);
                float c0 = fc[n0 * 32 + p], s0 = fs[n0 * 32 + p];
                float c1 = fc[n1 * 32 + p], s1 = fs[n1 * 32 + p];
                float xr0 = acc[mt][nt][0], xi0 = acc[mt][nt][1];
                float xr1 = acc[mt][nt][2], xi1 = acc[mt][nt][3];
                *(float2*)p0 = make_float2(roundtf(xr0 * c0 - xi0 * s0),
                                           roundtf(xr0 * s0 + xi0 * c0));
                *(float2*)p1 = make_float2(roundtf(xr1 * c1 - xi1 * s1),
                                           roundtf(xr1 * s1 + xi1 * c1));
            } else {
                *(float2*)p0 = make_float2(roundtf(acc[mt][nt][0]),
                                           roundtf(acc[mt][nt][1]));
                *(float2*)p1 = make_float2(roundtf(acc[mt][nt][2]),
                                           roundtf(acc[mt][nt][3]));
            }
        }
    }
}

// Plain GEMM for the output projection (BK=32, 3-stage).
__global__ __launch_bounds__(256, 2) void tf32gemm(
    const float* __restrict__ A, const float* __restrict__ B,
    float* __restrict__ C, int M, int N, int K)
{
    extern __shared__ float smf[];

    const int tid  = threadIdx.x;
    const int lane = tid & 31;
    const int wid  = tid >> 5;
    const int wm   = wid & 3;
    const int wn   = wid >> 2;
    const int gid  = lane >> 2;
    const int tig  = lane & 3;

    const float* Ab = A + (size_t)(blockIdx.y * 128) * K;
    const float* Bb = B + blockIdx.x * 128;

    auto load_stage = [&](int kt, int s) {
        float* Ad = smf + s * GST;
        float* Bd = smf + s * GST + A_ST;
        const int k0 = kt * 32;
#pragma unroll
        for (int i = 0; i < 4; i++) {
            int c = tid + i * 256;
            int ar = c >> 3, akq = (c & 7) << 2;
            cp_async16(Ad + ar * APAD + akq, Ab + (size_t)ar * K + k0 + akq);
            int br = c >> 5, bnq = (c & 31) << 2;
            cp_async16(Bd + br * BPAD + bnq, Bb + (size_t)(k0 + br) * N + bnq);
        }
    };

    float acc[2][8][4];
#pragma unroll
    for (int mt = 0; mt < 2; mt++)
#pragma unroll
        for (int nt = 0; nt < 8; nt++)
#pragma unroll
            for (int i = 0; i < 4; i++) acc[mt][nt][i] = 0.f;

    const int nk = K / 32;
    load_stage(0, 0); CP_COMMIT();
    load_stage(1, 1); CP_COMMIT();

    int st = 0;
    for (int kt = 0; kt < nk; kt++) {
        if (kt < nk - 1) { CP_WAIT1(); } else { CP_WAIT0(); }
        __syncthreads();

        if (kt + 2 < nk) {
            int s2 = st + 2; if (s2 >= 3) s2 -= 3;
            load_stage(kt + 2, s2);
            CP_COMMIT();
        }

        const float* Asb = smf + st * GST;
        const float* Bsb = smf + st * GST + A_ST;
#pragma unroll
        for (int ks = 0; ks < 4; ks++) {
            const int k0 = ks * 8;
            uint32_t a[2][4];
#pragma unroll
            for (int mt = 0; mt < 2; mt++) {
                const int mr = wm * 32 + mt * 16;
                a[mt][0] = __float_as_uint(Asb[(mr + gid) * APAD + k0 + tig]);
                a[mt][1] = __float_as_uint(Asb[(mr + gid + 8) * APAD + k0 + tig]);
                a[mt][2] = __float_as_uint(Asb[(mr + gid) * APAD + k0 + tig + 4]);
                a[mt][3] = __float_as_uint(Asb[(mr + gid + 8) * APAD + k0 + tig + 4]);
            }
            uint32_t b[8][2];
#pragma unroll
            for (int nt = 0; nt < 8; nt++) {
                const int nc = wn * 64 + nt * 8 + gid;
                b[nt][0] = __float_as_uint(Bsb[(k0 + tig) * BPAD + nc]);
                b[nt][1] = __float_as_uint(Bsb[(k0 + tig + 4) * BPAD + nc]);
            }
#pragma unroll
            for (int mt = 0; mt < 2; mt++)
#pragma unroll
                for (int nt = 0; nt < 8; nt++)
                    mma_tf32(acc[mt][nt], a[mt], b[nt]);
        }
        st++; if (st == 3) st = 0;
    }

    const int cm = blockIdx.y * 128 + wm * 32;
    const int cn = blockIdx.x * 128 + wn * 64;
#pragma unroll
    for (int mt = 0; mt < 2; mt++) {
#pragma unroll
        for (int nt = 0; nt < 8; nt++) {
            float* p0 = C + (size_t)(cm + mt * 16 + gid) * N + cn + nt * 8 + 2 * tig;
            float* p1 = p0 + (size_t)8 * N;
            *(float2*)p0 = make_float2(acc[mt][nt][0], acc[mt][nt][1]);
            *(float2*)p1 = make_float2(acc[mt][nt][2], acc[mt][nt][3]);
        }
    }
}

// ---------------------------------------------------------------------------
// Tensor-core flash attention (tf32), causal, GQA. LPT schedule.
// ---------------------------------------------------------------------------
#define KPITCH 68
#define VPITCH 72
#define PPITCH 68
#define KBUF (64 * KPITCH)
#define VBUF (64 * VPITCH)
#define SMEM_ATTN ((2 * KBUF + 2 * VBUF + 4 * 16 * PPITCH) * 4)

__global__ __launch_bounds__(128) void attn_tc(
    const float* __restrict__ Q, const float* __restrict__ Kg,
    const float* __restrict__ Vg, float* __restrict__ O)
{
    extern __shared__ char smem_raw[];
    float*    sK = (float*)smem_raw;
    float*    sV = (float*)(smem_raw + 2 * KBUF * 4);
    uint32_t* sP = (uint32_t*)(smem_raw + (2 * KBUF + 2 * VBUF) * 4);

    const int qt = NQT - 1 - blockIdx.x;   // LPT: big tiles first
    const int h = blockIdx.y, b = blockIdx.z;
    const int kvh = h >> 2;
    const int tid = threadIdx.x;
    const int w = tid >> 5;
    const int lane = tid & 31;
    const int gid = lane >> 2, tig = lane & 3;

    const int qr0 = qt * 64 + w * 16 + gid;
    const int qr1 = qr0 + 8;

    uint32_t aq[8][4];
    {
        const float* q0 = Q + ((size_t)(b * NSEQ) + qr0) * DMODEL + h * HD;
        const float* q1 = Q + ((size_t)(b * NSEQ) + qr1) * DMODEL + h * HD;
#pragma unroll
        for (int ks = 0; ks < 8; ks++) {
            int d = ks * 8 + tig;
            aq[ks][0] = __float_as_uint(q0[d] * 0.125f);
            aq[ks][1] = __float_as_uint(q1[d] * 0.125f);
            aq[ks][2] = __float_as_uint(q0[d + 4] * 0.125f);
            aq[ks][3] = __float_as_uint(q1[d + 4] * 0.125f);
        }
    }

    float o[8][4];
#pragma unroll
    for (int nt = 0; nt < 8; nt++)
#pragma unroll
        for (int i = 0; i < 4; i++) o[nt][i] = 0.f;
    float m0 = -1e30f, l0 = 0.f, m1 = -1e30f, l1 = 0.f;

    const size_t kvs = NKVH * HD;

    auto load_tile = [&](int t, int st) {
        const float* kb = Kg + (size_t)(b * NSEQ + t * 64) * kvs + kvh * HD;
        const float* vb = Vg + (size_t)(b * NSEQ + t * 64) * kvs + kvh * HD;
        float* dK = sK + st * KBUF;
        float* dV = sV + st * VBUF;
#pragma unroll
        for (int i = 0; i < 8; i++) {
            int c = tid + i * 128;
            int r = c >> 4, c4 = (c & 15) << 2;
            cp_async16(dK + r * KPITCH + c4, kb + (size_t)r * kvs + c4);
            cp_async16(dV + r * VPITCH + c4, vb + (size_t)r * kvs + c4);
        }
    };

    load_tile(0, 0);
    CP_COMMIT();

    for (int t = 0; t <= qt; t++) {
        const int st = t & 1;
        CP_WAIT0();
        __syncthreads();

        if (t < qt) { load_tile(t + 1, st ^ 1); CP_COMMIT(); }

        const float* bK = sK + st * KBUF;
        const float* bV = sV + st * VBUF;

        float s[8][4];
#pragma unroll
        for (int nt = 0; nt < 8; nt++)
#pragma unroll
            for (int i = 0; i < 4; i++) s[nt][i] = 0.f;
#pragma unroll
        for (int ks = 0; ks < 8; ks++) {
            const int d0 = ks * 8;
#pragma unroll
            for (int nt = 0; nt < 8; nt++) {
                const float* kr = bK + (nt * 8 + gid) * KPITCH + d0 + tig;
                uint32_t bb[2];
                bb[0] = __float_as_uint(kr[0]);
                bb[1] = __float_as_uint(kr[4]);
                mma_tf32(s[nt], aq[ks], bb);
            }
        }

        if (t == qt) {
#pragma unroll
            for (int nt = 0; nt < 8; nt++) {
                int k0 = nt * 8 + 2 * tig;
                int r0 = w * 16 + gid;
                if (k0 > r0)         s[nt][0] = -1e30f;
                if (k0 + 1 > r0)     s[nt][1] = -1e30f;
                if (k0 > r0 + 8)     s[nt][2] = -1e30f;
                if (k0 + 1 > r0 + 8) s[nt][3] = -1e30f;
            }
        }

        float mx0 = -1e30f, mx1 = -1e30f;
#pragma unroll
        for (int nt = 0; nt < 8; nt++) {
            mx0 = fmaxf(mx0, fmaxf(s[nt][0], s[nt][1]));
            mx1 = fmaxf(mx1, fmaxf(s[nt][2], s[nt][3]));
        }
        mx0 = fmaxf(mx0, __shfl_xor_sync(0xffffffffu, mx0, 1));
        mx0 = fmaxf(mx0, __shfl_xor_sync(0xffffffffu, mx0, 2));
        mx1 = fmaxf(mx1, __shfl_xor_sync(0xffffffffu, mx1, 1));
        mx1 = fmaxf(mx1, __shfl_xor_sync(0xffffffffu, mx1, 2));

        float mn0 = fmaxf(m0, mx0), mn1 = fmaxf(m1, mx1);
        float c0 = __expf(m0 - mn0), c1 = __expf(m1 - mn1);
        float ls0 = 0.f, ls1 = 0.f;
#pragma unroll
        for (int nt = 0; nt < 8; nt++) {
            s[nt][0] = __expf(s[nt][0] - mn0);
            s[nt][1] = __expf(s[nt][1] - mn0);
            s[nt][2] = __expf(s[nt][2] - mn1);
            s[nt][3] = __expf(s[nt][3] - mn1);
            ls0 += s[nt][0] + s[nt][1];
            ls1 += s[nt][2] + s[nt][3];
        }
        ls0 += __shfl_xor_sync(0xffffffffu, ls0, 1);
        ls0 += __shfl_xor_sync(0xffffffffu, ls0, 2);
        ls1 += __shfl_xor_sync(0xffffffffu, ls1, 1);
        ls1 += __shfl_xor_sync(0xffffffffu, ls1, 2);
        l0 = l0 * c0 + ls0;
        l1 = l1 * c1 + ls1;
        m0 = mn0; m1 = mn1;
#pragma unroll
        for (int nt = 0; nt < 8; nt++) {
            o[nt][0] *= c0; o[nt][1] *= c0;
            o[nt][2] *= c1; o[nt][3] *= c1;
        }

        uint32_t* pw = sP + w * (16 * PPITCH);
#pragma unroll
        for (int nt = 0; nt < 8; nt++) {
            uint2 v0 = make_uint2(f2tf32(s[nt][0]), f2tf32(s[nt][1]));
            uint2 v1 = make_uint2(f2tf32(s[nt][2]), f2tf32(s[nt][3]));
            *(uint2*)(pw + gid * PPITCH + nt * 8 + 2 * tig) = v0;
            *(uint2*)(pw + (gid + 8) * PPITCH + nt * 8 + 2 * tig) = v1;
        }
        __syncwarp();

#pragma unroll
        for (int ks = 0; ks < 8; ks++) {
            const int k0 = ks * 8;
            uint32_t ap[4];
            ap[0] = pw[gid * PPITCH + k0 + tig];
            ap[1] = pw[(gid + 8) * PPITCH + k0 + tig];
            ap[2] = pw[gid * PPITCH + k0 + tig + 4];
            ap[3] = pw[(gid + 8) * PPITCH + k0 + tig + 4];
#pragma unroll
            for (int nt = 0; nt < 8; nt++) {
                const float* vr = bV + (k0 + tig) * VPITCH + nt * 8 + gid;
                uint32_t bb[2];
                bb[0] = __float_as_uint(vr[0]);
                bb[1] = __float_as_uint(vr[4 * VPITCH]);
                mma_tf32(o[nt], ap, bb);
            }
        }
    }

    float inv0 = 1.f / l0, inv1 = 1.f / l1;
    float* o0 = O + ((size_t)(b * NSEQ) + qr0) * DMODEL + h * HD;
    float* o1 = O + ((size_t)(b * NSEQ) + qr1) * DMODEL + h * HD;
#pragma unroll
    for (int nt = 0; nt < 8; nt++) {
        *(float2*)(o0 + nt * 8 + 2 * tig) =
            make_float2(roundtf(o[nt][0] * inv0), roundtf(o[nt][1] * inv0));
        *(float2*)(o1 + nt * 8 + 2 * tig) =
            make_float2(roundtf(o[nt][2] * inv1), roundtf(o[nt][3] * inv1));
    }
}

// ---------------------------------------------------------------------------
// Launch. Order: round_all(1), qkv(2), attn(3), O-gemm(4 = ncu slot).
// ---------------------------------------------------------------------------
extern "C" void kernel_launch(void* const* d_in, const int* in_sizes, int n_in,
                              void* d_out, int out_size)
{
    const float* x  = (const float*)d_in[0];
    const float* Wq = (const float*)d_in[1];
    const float* Wk = (const float*)d_in[2];
    const float* Wv = (const float*)d_in[3];
    const float* Wo = (const float*)d_in[4];
    const float* fc = (const float*)d_in[5];
    const float* fs = (const float*)d_in[6];
    float* out = (float*)d_out;

    float *Qp, *Kp, *Vp, *Op, *xr, *Wqr, *Wkr, *Wvr, *Wor;
    cudaGetSymbolAddress((void**)&Qp,  g_Q);
    cudaGetSymbolAddress((void**)&Kp,  g_K);
    cudaGetSymbolAddress((void**)&Vp,  g_V);
    cudaGetSymbolAddress((void**)&Op,  g_O);
    cudaGetSymbolAddress((void**)&xr,  g_xr);
    cudaGetSymbolAddress((void**)&Wqr, g_Wqr);
    cudaGetSymbolAddress((void**)&Wkr, g_Wkr);
    cudaGetSymbolAddress((void**)&Wvr, g_Wvr);
    cudaGetSymbolAddress((void**)&Wor, g_Wor);

    static bool attr_set = false;
    if (!attr_set) {
        cudaFuncSetAttribute(attn_tc,
            cudaFuncAttributeMaxDynamicSharedMemorySize, SMEM_ATTN);
        cudaFuncSetAttribute(qkv_gemm,
            cudaFuncAttributeMaxDynamicSharedMemorySize, GEMM_DYN);
        cudaFuncSetAttribute(tf32gemm,
            cudaFuncAttributeMaxDynamicSharedMemorySize, GEMM_DYN);
        attr_set = true;
    }

    // 1: fused tf32 rounding
    round_all<<<(N4_ALL + 255) / 256, 256>>>(
        (const float4*)x, (const float4*)Wq, (const float4*)Wk,
        (const float4*)Wv, (const float4*)Wo,
        (float4*)xr, (float4*)Wqr, (float4*)Wkr, (float4*)Wvr, (float4*)Wor);

    // 2: fused Q/K/V projection + RoPE
    qkv_gemm<<<dim3(24, ROWS / 128), 256, GEMM_DYN>>>(
        xr, Wqr, Wkr, Wvr, Qp, Kp, Vp, fc, fs);

    // 3: attention (LPT-ordered)
    attn_tc<<<dim3(NQT, NH, BATCH), 128, SMEM_ATTN>>>(Qp, Kp, Vp, Op);

    // 4: output projection  <-- ncu capture slot
    tf32gemm<<<dim3(DMODEL / 128, ROWS / 128), 256, GEMM_DYN>>>(
        Op, Wor, out, ROWS, DMODEL, DMODEL);
}